// round 4
// baseline (speedup 1.0000x reference)
#include <cuda_runtime.h>

#define B_  4
#define S_  2048
#define D_  512
#define H_  8
#define DH_ 64
#define BH_ (B_ * H_)

typedef unsigned long long ull;

__device__ float g_q[B_ * H_ * S_ * DH_];
__device__ float g_k[B_ * H_ * S_ * DH_];
__device__ float g_v[B_ * H_ * S_ * DH_];

__device__ __forceinline__ ull ffma2(ull a, ull b, ull c) {
    ull d;
    asm("fma.rn.f32x2 %0, %1, %2, %3;" : "=l"(d) : "l"(a), "l"(b), "l"(c));
    return d;
}
__device__ __forceinline__ ull fmul2(ull a, ull b) {
    ull d;
    asm("mul.rn.f32x2 %0, %1, %2;" : "=l"(d) : "l"(a), "l"(b));
    return d;
}
__device__ __forceinline__ ull pack2(float lo, float hi) {
    ull d;
    asm("mov.b64 %0, {%1, %2};" : "=l"(d) : "f"(lo), "f"(hi));
    return d;
}
__device__ __forceinline__ float2 unpack2(ull v) {
    float lo, hi;
    asm("mov.b64 {%0, %1}, %2;" : "=f"(lo), "=f"(hi) : "l"(v));
    return make_float2(lo, hi);
}

// ---------------------------------------------------------------------------
// Kernel A: fused QKV projection, packed-FFMA2.
//   Tile 128(M) x 64(N), K=512, BK=16, 256 threads.
//   Micro-tile: 8 M (4 f32x2 pairs) x 4 N per thread.
//   Xs: k-major transposed [k][m] (natural M pairs).
//   Wd: duplicated [k][2n] so the scalar side loads as ready-made f32x2.
// ---------------------------------------------------------------------------
__global__ __launch_bounds__(256) void qkv_kernel(
    const float* __restrict__ x,
    const float* __restrict__ Wq,
    const float* __restrict__ Wk,
    const float* __restrict__ Wv)
{
    __shared__ float Xs[16 * 128];
    __shared__ float Wd[16 * 128];

    const int t  = threadIdx.x;
    const int tx = t & 15;               // n group: cols tx*4..+3
    const int ty = t >> 4;               // m group: rows ty*8..+7
    const int m0 = blockIdx.x * 128;
    const int wh = blockIdx.y;           // (weight)*8 + head
    const int w  = wh >> 3;
    const int h  = wh & 7;

    const float* W   = (w == 0 ? Wq : (w == 1 ? Wk : Wv)) + h * D_ * DH_;
    float*       out = (w == 0 ? g_q : (w == 1 ? g_k : g_v));

    const int xr = t >> 1;               // 0..127
    const int xc = (t & 1) * 8;          // k offset base
    const int wr = t >> 4;               // 0..15
    const int wc = (t & 15) * 4;         // 0..60

    ull acc[4][4] = {};

    for (int k0 = 0; k0 < D_; k0 += 16) {
        #pragma unroll
        for (int it = 0; it < 2; it++) {
            int c = xc + it * 4;
            float4 xv = *reinterpret_cast<const float4*>(&x[(m0 + xr) * D_ + k0 + c]);
            Xs[(c + 0) * 128 + xr] = xv.x;
            Xs[(c + 1) * 128 + xr] = xv.y;
            Xs[(c + 2) * 128 + xr] = xv.z;
            Xs[(c + 3) * 128 + xr] = xv.w;
        }
        {
            float4 wv = *reinterpret_cast<const float4*>(&W[(k0 + wr) * DH_ + wc]);
            *reinterpret_cast<ull*>(&Wd[wr * 128 + 2 * (wc + 0)]) = pack2(wv.x, wv.x);
            *reinterpret_cast<ull*>(&Wd[wr * 128 + 2 * (wc + 1)]) = pack2(wv.y, wv.y);
            *reinterpret_cast<ull*>(&Wd[wr * 128 + 2 * (wc + 2)]) = pack2(wv.z, wv.z);
            *reinterpret_cast<ull*>(&Wd[wr * 128 + 2 * (wc + 3)]) = pack2(wv.w, wv.w);
        }
        __syncthreads();

        #pragma unroll
        for (int kk = 0; kk < 16; kk++) {
            ulonglong2 A0 = *reinterpret_cast<const ulonglong2*>(&Xs[kk * 128 + ty * 8]);
            ulonglong2 A1 = *reinterpret_cast<const ulonglong2*>(&Xs[kk * 128 + ty * 8 + 4]);
            ulonglong2 B0 = *reinterpret_cast<const ulonglong2*>(&Wd[kk * 128 + tx * 8]);
            ulonglong2 B1 = *reinterpret_cast<const ulonglong2*>(&Wd[kk * 128 + tx * 8 + 4]);
            ull a[4] = {A0.x, A0.y, A1.x, A1.y};
            ull b[4] = {B0.x, B0.y, B1.x, B1.y};
            #pragma unroll
            for (int p = 0; p < 4; p++)
                #pragma unroll
                for (int j = 0; j < 4; j++)
                    acc[p][j] = ffma2(a[p], b[j], acc[p][j]);
        }
        __syncthreads();
    }

    #pragma unroll
    for (int p = 0; p < 4; p++) {
        float2 f0 = unpack2(acc[p][0]);
        float2 f1 = unpack2(acc[p][1]);
        float2 f2 = unpack2(acc[p][2]);
        float2 f3 = unpack2(acc[p][3]);
        int m_lo = m0 + ty * 8 + 2 * p;
        #pragma unroll
        for (int hh = 0; hh < 2; hh++) {
            int m = m_lo + hh;
            int b = m >> 11;
            int s = m & (S_ - 1);
            float4 o4 = hh == 0 ? make_float4(f0.x, f1.x, f2.x, f3.x)
                                : make_float4(f0.y, f1.y, f2.y, f3.y);
            *reinterpret_cast<float4*>(
                &out[(((b * H_ + h) * S_) + s) * DH_ + tx * 4]) = o4;
        }
    }
}

// ---------------------------------------------------------------------------
// Kernel B: flash attention, packed-FFMA2.
//   Q-tile 128, K-tile 64, 256 threads. Micro: 8 qi (4 pairs) x 4 kj / 4 d.
//   Qt : [d][qi]   transposed, scaled by DH^-0.5 (natural qi pairs)
//   Kd : [d][2kj]  duplicated
//   Vd : [kj][2d]  duplicated
//   Pt : [kj][qi]  transposed, stride 132 (natural qi pairs)
// ---------------------------------------------------------------------------
#define PPAD 132
#define ATTN_SMEM ((3 * 64 * 128 + 64 * PPAD) * 4)

__global__ __launch_bounds__(256, 1) void attn_kernel(float* __restrict__ out)
{
    extern __shared__ float sm[];
    float* Qt = sm;                    // 64*128
    float* Kd = sm + 64 * 128;         // 64*128
    float* Vd = sm + 2 * 64 * 128;     // 64*128
    float* Pt = sm + 3 * 64 * 128;     // 64*PPAD

    const int t  = threadIdx.x;
    const int tx = t & 15;             // kj group (S) / d group (O)
    const int ty = t >> 4;             // qi group
    const int q0 = blockIdx.x * 128;
    const int bh = blockIdx.y;

    const float* qp = g_q + bh * S_ * DH_;
    const float* kp = g_k + bh * S_ * DH_;
    const float* vp = g_v + bh * S_ * DH_;

    // Load Q tile, scaled, transposed: Qt[d][qi]
    {
        const int qi = t >> 1;
        #pragma unroll
        for (int it = 0; it < 8; it++) {
            int d0 = ((t & 1) * 8 + it) * 4;
            float4 qv = *reinterpret_cast<const float4*>(&qp[(q0 + qi) * DH_ + d0]);
            Qt[(d0 + 0) * 128 + qi] = qv.x * 0.125f;
            Qt[(d0 + 1) * 128 + qi] = qv.y * 0.125f;
            Qt[(d0 + 2) * 128 + qi] = qv.z * 0.125f;
            Qt[(d0 + 3) * 128 + qi] = qv.w * 0.125f;
        }
    }

    ull o[4][4] = {};
    float m_run[8], l_run[8];
    #pragma unroll
    for (int i = 0; i < 8; i++) { m_run[i] = -1e30f; l_run[i] = 0.0f; }

    const int kv_r = t >> 2;           // 0..63 (kj row)
    const int kv_c = (t & 3) * 16;     // d chunk base

    for (int kt = 0; kt < S_ / 64; kt++) {
        __syncthreads();               // prev iter readers done with Kd/Vd/Pt
        const int s0 = kt * 64;
        #pragma unroll
        for (int it = 0; it < 4; it++) {
            int d0 = kv_c + it * 4;
            float4 kv = *reinterpret_cast<const float4*>(&kp[(s0 + kv_r) * DH_ + d0]);
            float4 vv = *reinterpret_cast<const float4*>(&vp[(s0 + kv_r) * DH_ + d0]);
            *reinterpret_cast<ull*>(&Kd[(d0 + 0) * 128 + 2 * kv_r]) = pack2(kv.x, kv.x);
            *reinterpret_cast<ull*>(&Kd[(d0 + 1) * 128 + 2 * kv_r]) = pack2(kv.y, kv.y);
            *reinterpret_cast<ull*>(&Kd[(d0 + 2) * 128 + 2 * kv_r]) = pack2(kv.z, kv.z);
            *reinterpret_cast<ull*>(&Kd[(d0 + 3) * 128 + 2 * kv_r]) = pack2(kv.w, kv.w);
            *reinterpret_cast<ull*>(&Vd[kv_r * 128 + 2 * (d0 + 0)]) = pack2(vv.x, vv.x);
            *reinterpret_cast<ull*>(&Vd[kv_r * 128 + 2 * (d0 + 1)]) = pack2(vv.y, vv.y);
            *reinterpret_cast<ull*>(&Vd[kv_r * 128 + 2 * (d0 + 2)]) = pack2(vv.z, vv.z);
            *reinterpret_cast<ull*>(&Vd[kv_r * 128 + 2 * (d0 + 3)]) = pack2(vv.w, vv.w);
        }
        __syncthreads();

        // S = (Q*scale) @ K^T   (pairs along qi)
        ull sv[4][4] = {};
        #pragma unroll 8
        for (int d = 0; d < 64; d++) {
            ulonglong2 A0 = *reinterpret_cast<const ulonglong2*>(&Qt[d * 128 + ty * 8]);
            ulonglong2 A1 = *reinterpret_cast<const ulonglong2*>(&Qt[d * 128 + ty * 8 + 4]);
            ulonglong2 B0 = *reinterpret_cast<const ulonglong2*>(&Kd[d * 128 + tx * 8]);
            ulonglong2 B1 = *reinterpret_cast<const ulonglong2*>(&Kd[d * 128 + tx * 8 + 4]);
            ull a[4] = {A0.x, A0.y, A1.x, A1.y};
            ull b[4] = {B0.x, B0.y, B1.x, B1.y};
            #pragma unroll
            for (int p = 0; p < 4; p++)
                #pragma unroll
                for (int j = 0; j < 4; j++)
                    sv[p][j] = ffma2(a[p], b[j], sv[p][j]);
        }

        // Unpack to scalars for softmax
        float s[8][4];
        #pragma unroll
        for (int p = 0; p < 4; p++)
            #pragma unroll
            for (int j = 0; j < 4; j++) {
                float2 f = unpack2(sv[p][j]);
                s[2 * p + 0][j] = f.x;
                s[2 * p + 1][j] = f.y;
            }

        float alpha[8];
        #pragma unroll
        for (int i = 0; i < 8; i++) {
            float rm = fmaxf(fmaxf(s[i][0], s[i][1]), fmaxf(s[i][2], s[i][3]));
            #pragma unroll
            for (int off = 1; off < 16; off <<= 1)
                rm = fmaxf(rm, __shfl_xor_sync(0xffffffffu, rm, off));
            float mn = fmaxf(m_run[i], rm);
            alpha[i] = __expf(m_run[i] - mn);
            m_run[i] = mn;
            float rs = 0.0f;
            #pragma unroll
            for (int j = 0; j < 4; j++) {
                float p = __expf(s[i][j] - mn);
                s[i][j] = p;
                rs += p;
            }
            #pragma unroll
            for (int off = 1; off < 16; off <<= 1)
                rs += __shfl_xor_sync(0xffffffffu, rs, off);
            l_run[i] = l_run[i] * alpha[i] + rs;
        }

        // Rescale O (pairs along qi)
        #pragma unroll
        for (int p = 0; p < 4; p++) {
            ull ap = pack2(alpha[2 * p], alpha[2 * p + 1]);
            #pragma unroll
            for (int j = 0; j < 4; j++)
                o[p][j] = fmul2(o[p][j], ap);
        }

        // Store P transposed with qi pairs
        #pragma unroll
        for (int j = 0; j < 4; j++)
            #pragma unroll
            for (int p = 0; p < 4; p++)
                *reinterpret_cast<ull*>(&Pt[(tx * 4 + j) * PPAD + ty * 8 + 2 * p]) =
                    pack2(s[2 * p][j], s[2 * p + 1][j]);
        __syncthreads();

        // O += P @ V  (pairs along qi; V duplicated along d)
        #pragma unroll 8
        for (int kj = 0; kj < 64; kj++) {
            ulonglong2 A0 = *reinterpret_cast<const ulonglong2*>(&Pt[kj * PPAD + ty * 8]);
            ulonglong2 A1 = *reinterpret_cast<const ulonglong2*>(&Pt[kj * PPAD + ty * 8 + 4]);
            ulonglong2 B0 = *reinterpret_cast<const ulonglong2*>(&Vd[kj * 128 + tx * 8]);
            ulonglong2 B1 = *reinterpret_cast<const ulonglong2*>(&Vd[kj * 128 + tx * 8 + 4]);
            ull a[4] = {A0.x, A0.y, A1.x, A1.y};
            ull b[4] = {B0.x, B0.y, B1.x, B1.y};
            #pragma unroll
            for (int p = 0; p < 4; p++)
                #pragma unroll
                for (int j = 0; j < 4; j++)
                    o[p][j] = ffma2(a[p], b[j], o[p][j]);
        }
    }

    // Epilogue: normalize, write [B,S,H*DH]
    const int b = bh >> 3;
    const int h = bh & 7;
    #pragma unroll
    for (int p = 0; p < 4; p++) {
        float2 f0 = unpack2(o[p][0]);
        float2 f1 = unpack2(o[p][1]);
        float2 f2 = unpack2(o[p][2]);
        float2 f3 = unpack2(o[p][3]);
        #pragma unroll
        for (int hh = 0; hh < 2; hh++) {
            int i = 2 * p + hh;
            float inv = 1.0f / l_run[i];
            int sI = q0 + ty * 8 + i;
            float4 o4 = hh == 0
                ? make_float4(f0.x * inv, f1.x * inv, f2.x * inv, f3.x * inv)
                : make_float4(f0.y * inv, f1.y * inv, f2.y * inv, f3.y * inv);
            *reinterpret_cast<float4*>(
                &out[((b * S_ + sI) * H_ + h) * DH_ + tx * 4]) = o4;
        }
    }
}

extern "C" void kernel_launch(void* const* d_in, const int* in_sizes, int n_in,
                              void* d_out, int out_size)
{
    const float* x  = (const float*)d_in[0];
    const float* Wq = (const float*)d_in[1];
    const float* Wk = (const float*)d_in[2];
    const float* Wv = (const float*)d_in[3];
    float* out = (float*)d_out;

    cudaFuncSetAttribute(attn_kernel,
                         cudaFuncAttributeMaxDynamicSharedMemorySize, ATTN_SMEM);

    qkv_kernel<<<dim3((B_ * S_) / 128, 3 * H_), 256>>>(x, Wq, Wk, Wv);
    attn_kernel<<<dim3(S_ / 128, BH_), 256, ATTN_SMEM>>>(out);
}

// round 6
// speedup vs baseline: 3.0681x; 3.0681x over previous
#include <cuda_runtime.h>
#include <cuda_bf16.h>

typedef unsigned int u32;
typedef unsigned short u16;

// ------------------------- scratch -------------------------
__device__ u16 g_xh[8192 * 512];
__device__ u16 g_xl[8192 * 512];
__device__ u16 g_wth[24 * 64 * 512];   // [wh][n=dh][k=d] transposed
__device__ u16 g_wtl[24 * 64 * 512];
__device__ u16 g_qh[32 * 2048 * 64];   // [bh][s][dh]
__device__ u16 g_ql[32 * 2048 * 64];
__device__ u16 g_kh[32 * 2048 * 64];
__device__ u16 g_kl[32 * 2048 * 64];
__device__ u16 g_vth[32 * 64 * 2048];  // [bh][dh][s] transposed
__device__ u16 g_vtl[32 * 64 * 2048];

// ------------------------- helpers -------------------------
__device__ __forceinline__ float ex2f(float x) {
    float y;
    asm("ex2.approx.f32 %0, %1;" : "=f"(y) : "f"(x));
    return y;
}
// pack (f0,f1): hi = bf16x2{lower=f0, upper=f1}, lo = residuals
__device__ __forceinline__ void split2(float f0, float f1, u32& hi, u32& lo) {
    asm("cvt.rn.bf16x2.f32 %0, %1, %2;" : "=r"(hi) : "f"(f1), "f"(f0));
    float h0 = __uint_as_float(hi << 16);
    float h1 = __uint_as_float(hi & 0xffff0000u);
    asm("cvt.rn.bf16x2.f32 %0, %1, %2;" : "=r"(lo) : "f"(f1 - h1), "f"(f0 - h0));
}
__device__ __forceinline__ void mma16816(float* c,
                                         u32 a0, u32 a1, u32 a2, u32 a3,
                                         u32 b0, u32 b1) {
    asm volatile(
        "mma.sync.aligned.m16n8k16.row.col.f32.bf16.bf16.f32 "
        "{%0,%1,%2,%3}, {%4,%5,%6,%7}, {%8,%9}, {%0,%1,%2,%3};"
        : "+f"(c[0]), "+f"(c[1]), "+f"(c[2]), "+f"(c[3])
        : "r"(a0), "r"(a1), "r"(a2), "r"(a3), "r"(b0), "r"(b1));
}

// ------------------------- prep: split X -------------------------
__global__ __launch_bounds__(256) void split_x_kernel(const float* __restrict__ x) {
    int n4 = 8192 * 512 / 4;
    for (int i = blockIdx.x * 256 + threadIdx.x; i < n4; i += gridDim.x * 256) {
        float4 v = ((const float4*)x)[i];
        u32 h0, l0, h1, l1;
        split2(v.x, v.y, h0, l0);
        split2(v.z, v.w, h1, l1);
        ((uint2*)g_xh)[i] = make_uint2(h0, h1);
        ((uint2*)g_xl)[i] = make_uint2(l0, l1);
    }
}

// ------------------------- prep: transpose + split W -------------------------
__global__ __launch_bounds__(256) void split_w_kernel(
    const float* __restrict__ Wq, const float* __restrict__ Wk, const float* __restrict__ Wv) {
    __shared__ float tile[64][65];
    int wh = blockIdx.x, w = wh >> 3, h = wh & 7, t = threadIdx.x;
    const float* W = (w == 0 ? Wq : (w == 1 ? Wk : Wv)) + h * 512 * 64;
    float c = (w == 0) ? 0.125f * 1.4426950408889634f : 1.0f;  // fold scale*log2(e) into Wq
    for (int k0 = 0; k0 < 512; k0 += 64) {
        __syncthreads();
        for (int e = t; e < 4096; e += 256)
            tile[e >> 6][e & 63] = W[(k0 + (e >> 6)) * 64 + (e & 63)] * c;
        __syncthreads();
        for (int e = t; e < 4096; e += 256) {
            int n = e >> 6, kk = e & 63;
            float f = tile[kk][n];
            __nv_bfloat16 hb = __float2bfloat16(f);
            int o = (wh * 64 + n) * 512 + k0 + kk;
            g_wth[o] = *(u16*)&hb;
            __nv_bfloat16 lb = __float2bfloat16(f - __bfloat162float(hb));
            g_wtl[o] = *(u16*)&lb;
        }
    }
}

// --------------------------- QKV projection (HMMA) ---------------------------
// grid (64, 8): 128-row M tile x head. N=192 (Q|K|V), K=512 in 8 chunks of 64.
// 256 threads = 8 warps; warp w owns rows w*16..w*16+15.
#define QK_SMEM ((2 * 128 * 72 + 2 * 192 * 72) * 2)

__global__ __launch_bounds__(256) void qkv_mma_kernel() {
    extern __shared__ u16 sm[];
    u16* Xh = sm;                      // [128][72]
    u16* Xl = sm + 128 * 72;
    u16* Wh = sm + 2 * 128 * 72;       // [192][72]
    u16* Wl = sm + 2 * 128 * 72 + 192 * 72;

    int t = threadIdx.x, w = t >> 5, lane = t & 31;
    int g = lane >> 2, tg = lane & 3;
    int m0 = blockIdx.x * 128, h = blockIdx.y;

    float acc[24][4];
    #pragma unroll
    for (int n = 0; n < 24; n++)
        #pragma unroll
        for (int e = 0; e < 4; e++) acc[n][e] = 0.0f;

    for (int kb = 0; kb < 8; kb++) {
        int k0 = kb * 64;
        __syncthreads();
        for (int e = t; e < 1024; e += 256) {
            int r = e >> 3, u = e & 7;
            *(uint4*)(Xh + r * 72 + u * 8) = *(const uint4*)(g_xh + (m0 + r) * 512 + k0 + u * 8);
            *(uint4*)(Xl + r * 72 + u * 8) = *(const uint4*)(g_xl + (m0 + r) * 512 + k0 + u * 8);
        }
        for (int e = t; e < 1536; e += 256) {
            int r = e >> 3, u = e & 7;
            int src = (((r >> 6) * 8 + h) * 64 + (r & 63)) * 512 + k0 + u * 8;
            *(uint4*)(Wh + r * 72 + u * 8) = *(const uint4*)(g_wth + src);
            *(uint4*)(Wl + r * 72 + u * 8) = *(const uint4*)(g_wtl + src);
        }
        __syncthreads();

        #pragma unroll
        for (int kc = 0; kc < 4; kc++) {
            const u16* x0 = Xh + (w * 16 + g) * 72 + kc * 16 + 2 * tg;
            const u16* x1 = x0 + 8 * 72;
            const u16* y0 = Xl + (w * 16 + g) * 72 + kc * 16 + 2 * tg;
            const u16* y1 = y0 + 8 * 72;
            u32 ah0 = *(const u32*)x0, ah1 = *(const u32*)x1;
            u32 ah2 = *(const u32*)(x0 + 8), ah3 = *(const u32*)(x1 + 8);
            u32 al0 = *(const u32*)y0, al1 = *(const u32*)y1;
            u32 al2 = *(const u32*)(y0 + 8), al3 = *(const u32*)(y1 + 8);
            #pragma unroll
            for (int nt = 0; nt < 24; nt++) {
                const u16* wp = Wh + (nt * 8 + g) * 72 + kc * 16 + 2 * tg;
                const u16* vp = Wl + (nt * 8 + g) * 72 + kc * 16 + 2 * tg;
                u32 bh0 = *(const u32*)wp, bh1 = *(const u32*)(wp + 8);
                u32 bl0 = *(const u32*)vp, bl1 = *(const u32*)(vp + 8);
                mma16816(acc[nt], ah0, ah1, ah2, ah3, bh0, bh1);
                mma16816(acc[nt], al0, al1, al2, al3, bh0, bh1);
                mma16816(acc[nt], ah0, ah1, ah2, ah3, bl0, bl1);
            }
        }
    }

    // epilogue: rows m (c0,c1) and m+8 (c2,c3)
    int m = m0 + w * 16 + g;
    int b = m >> 11, s = m & 2047, bh = b * 8 + h;
    #pragma unroll
    for (int wi = 0; wi < 3; wi++) {
        #pragma unroll
        for (int ntl = 0; ntl < 8; ntl++) {
            float c0 = acc[wi * 8 + ntl][0], c1 = acc[wi * 8 + ntl][1];
            float c2 = acc[wi * 8 + ntl][2], c3 = acc[wi * 8 + ntl][3];
            if (wi < 2) {
                u32* oh = (u32*)(wi == 0 ? g_qh : g_kh);
                u32* ol = (u32*)(wi == 0 ? g_ql : g_kl);
                u32 hw, lw;
                split2(c0, c1, hw, lw);
                int i0 = (bh * 2048 + s) * 32 + ntl * 4 + tg;
                oh[i0] = hw; ol[i0] = lw;
                split2(c2, c3, hw, lw);
                int i1 = i0 + 8 * 32;
                oh[i1] = hw; ol[i1] = lw;
            } else {
                int d0 = ntl * 8 + 2 * tg;
                float cv[4] = {c0, c1, c2, c3};
                #pragma unroll
                for (int e = 0; e < 4; e++) {
                    int d = d0 + (e & 1), ss = s + (e >> 1) * 8;
                    __nv_bfloat16 hb = __float2bfloat16(cv[e]);
                    __nv_bfloat16 lb = __float2bfloat16(cv[e] - __bfloat162float(hb));
                    g_vth[(bh * 64 + d) * 2048 + ss] = *(u16*)&hb;
                    g_vtl[(bh * 64 + d) * 2048 + ss] = *(u16*)&lb;
                }
            }
        }
    }
}

// ----------------------------- attention (HMMA) -----------------------------
// grid (16, 32): 128-query tile x (b*8+h). 8 warps; warp w owns 16 query rows.
// 16 KV tiles of 128. No-max softmax; O accumulates in registers.
#define AT_SMEM ((2 * 128 * 72 + 2 * 128 * 72 + 2 * 64 * 136) * 2)

__global__ __launch_bounds__(256) void attn_mma_kernel(float* __restrict__ out) {
    extern __shared__ u16 sm[];
    u16* Qh = sm;                        // [128][72]
    u16* Ql = sm + 128 * 72;
    u16* Kh = sm + 2 * 128 * 72;         // [128][72]
    u16* Kl = sm + 3 * 128 * 72;
    u16* Vh = sm + 4 * 128 * 72;         // [64][136]  (V^T: [d][kv])
    u16* Vl = sm + 4 * 128 * 72 + 64 * 136;

    int t = threadIdx.x, w = t >> 5, lane = t & 31;
    int g = lane >> 2, tg = lane & 3;
    int q0 = blockIdx.x * 128, bh = blockIdx.y;

    // load Q tile (hi/lo)
    for (int e = t; e < 1024; e += 256) {
        int r = e >> 3, u = e & 7;
        int src = (bh * 2048 + q0 + r) * 64 + u * 8;
        *(uint4*)(Qh + r * 72 + u * 8) = *(const uint4*)(g_qh + src);
        *(uint4*)(Ql + r * 72 + u * 8) = *(const uint4*)(g_ql + src);
    }
    __syncthreads();

    // preload Q A-fragments (held in registers across all tiles)
    u32 qah[4][4], qal[4][4];
    #pragma unroll
    for (int kc = 0; kc < 4; kc++) {
        const u16* x0 = Qh + (w * 16 + g) * 72 + kc * 16 + 2 * tg;
        const u16* y0 = Ql + (w * 16 + g) * 72 + kc * 16 + 2 * tg;
        qah[kc][0] = *(const u32*)x0;        qah[kc][1] = *(const u32*)(x0 + 8 * 72);
        qah[kc][2] = *(const u32*)(x0 + 8);  qah[kc][3] = *(const u32*)(x0 + 8 * 72 + 8);
        qal[kc][0] = *(const u32*)y0;        qal[kc][1] = *(const u32*)(y0 + 8 * 72);
        qal[kc][2] = *(const u32*)(y0 + 8);  qal[kc][3] = *(const u32*)(y0 + 8 * 72 + 8);
    }

    float oacc[8][4];
    #pragma unroll
    for (int n = 0; n < 8; n++)
        #pragma unroll
        for (int e = 0; e < 4; e++) oacc[n][e] = 0.0f;
    float l0 = 0.0f, l1 = 0.0f;

    for (int kt = 0; kt < 16; kt++) {
        int s0 = kt * 128;
        __syncthreads();
        for (int e = t; e < 1024; e += 256) {
            int r = e >> 3, u = e & 7;
            int src = (bh * 2048 + s0 + r) * 64 + u * 8;
            *(uint4*)(Kh + r * 72 + u * 8) = *(const uint4*)(g_kh + src);
            *(uint4*)(Kl + r * 72 + u * 8) = *(const uint4*)(g_kl + src);
        }
        for (int e = t; e < 1024; e += 256) {
            int d = e >> 4, u = e & 15;
            int src = (bh * 64 + d) * 2048 + s0 + u * 8;
            *(uint4*)(Vh + d * 136 + u * 8) = *(const uint4*)(g_vth + src);
            *(uint4*)(Vl + d * 136 + u * 8) = *(const uint4*)(g_vtl + src);
        }
        __syncthreads();

        #pragma unroll
        for (int half = 0; half < 2; half++) {
            // S = Q K^T for kv columns [half*64, half*64+64)
            float sacc[8][4];
            #pragma unroll
            for (int n = 0; n < 8; n++)
                #pragma unroll
                for (int e = 0; e < 4; e++) sacc[n][e] = 0.0f;

            #pragma unroll
            for (int nt = 0; nt < 8; nt++) {
                int kvrow = (half * 8 + nt) * 8 + g;
                #pragma unroll
                for (int kc = 0; kc < 4; kc++) {
                    const u16* kp = Kh + kvrow * 72 + kc * 16 + 2 * tg;
                    const u16* lp = Kl + kvrow * 72 + kc * 16 + 2 * tg;
                    u32 bh0 = *(const u32*)kp, bh1 = *(const u32*)(kp + 8);
                    u32 bl0 = *(const u32*)lp, bl1 = *(const u32*)(lp + 8);
                    mma16816(sacc[nt], qah[kc][0], qah[kc][1], qah[kc][2], qah[kc][3], bh0, bh1);
                    mma16816(sacc[nt], qal[kc][0], qal[kc][1], qal[kc][2], qal[kc][3], bh0, bh1);
                    mma16816(sacc[nt], qah[kc][0], qah[kc][1], qah[kc][2], qah[kc][3], bl0, bl1);
                }
            }
            // softmax numerators (scores already * log2e): p = 2^s
            #pragma unroll
            for (int nt = 0; nt < 8; nt++) {
                sacc[nt][0] = ex2f(sacc[nt][0]);
                sacc[nt][1] = ex2f(sacc[nt][1]);
                sacc[nt][2] = ex2f(sacc[nt][2]);
                sacc[nt][3] = ex2f(sacc[nt][3]);
                l0 += sacc[nt][0] + sacc[nt][1];
                l1 += sacc[nt][2] + sacc[nt][3];
            }
            // O += P V  (P reused from registers as A fragments)
            #pragma unroll
            for (int c = 0; c < 4; c++) {
                u32 ah0, al0, ah1, al1, ah2, al2, ah3, al3;
                split2(sacc[2 * c][0],     sacc[2 * c][1],     ah0, al0);
                split2(sacc[2 * c][2],     sacc[2 * c][3],     ah1, al1);
                split2(sacc[2 * c + 1][0], sacc[2 * c + 1][1], ah2, al2);
                split2(sacc[2 * c + 1][2], sacc[2 * c + 1][3], ah3, al3);
                int col = half * 64 + c * 16 + 2 * tg;
                #pragma unroll
                for (int dt = 0; dt < 8; dt++) {
                    const u16* vp = Vh + (dt * 8 + g) * 136 + col;
                    const u16* up = Vl + (dt * 8 + g) * 136 + col;
                    u32 bh0 = *(const u32*)vp, bh1 = *(const u32*)(vp + 8);
                    u32 bl0 = *(const u32*)up, bl1 = *(const u32*)(up + 8);
                    mma16816(oacc[dt], ah0, ah1, ah2, ah3, bh0, bh1);
                    mma16816(oacc[dt], al0, al1, al2, al3, bh0, bh1);
                    mma16816(oacc[dt], ah0, ah1, ah2, ah3, bl0, bl1);
                }
            }
        }
    }

    // row-sum reduce across the 4 threads of each row group
    l0 += __shfl_xor_sync(0xffffffffu, l0, 1);
    l0 += __shfl_xor_sync(0xffffffffu, l0, 2);
    l1 += __shfl_xor_sync(0xffffffffu, l1, 1);
    l1 += __shfl_xor_sync(0xffffffffu, l1, 2);
    float inv0 = 1.0f / l0, inv1 = 1.0f / l1;

    int b = bh >> 3, h = bh & 7;
    int s = q0 + w * 16 + g;
    float* o0 = out + ((b * 2048 + s) * 8 + h) * 64;
    float* o1 = out + ((b * 2048 + s + 8) * 8 + h) * 64;
    #pragma unroll
    for (int dt = 0; dt < 8; dt++) {
        *(float2*)(o0 + dt * 8 + 2 * tg) = make_float2(oacc[dt][0] * inv0, oacc[dt][1] * inv0);
        *(float2*)(o1 + dt * 8 + 2 * tg) = make_float2(oacc[dt][2] * inv1, oacc[dt][3] * inv1);
    }
}

extern "C" void kernel_launch(void* const* d_in, const int* in_sizes, int n_in,
                              void* d_out, int out_size)
{
    const float* x  = (const float*)d_in[0];
    const float* Wq = (const float*)d_in[1];
    const float* Wk = (const float*)d_in[2];
    const float* Wv = (const float*)d_in[3];
    float* out = (float*)d_out;

    cudaFuncSetAttribute(qkv_mma_kernel,  cudaFuncAttributeMaxDynamicSharedMemorySize, QK_SMEM);
    cudaFuncSetAttribute(attn_mma_kernel, cudaFuncAttributeMaxDynamicSharedMemorySize, AT_SMEM);

    split_x_kernel<<<512, 256>>>(x);
    split_w_kernel<<<24, 256>>>(Wq, Wk, Wv);
    qkv_mma_kernel<<<dim3(64, 8), 256, QK_SMEM>>>();
    attn_mma_kernel<<<dim3(16, 32), 256, AT_SMEM>>>(out);
}

// round 7
// speedup vs baseline: 4.1822x; 1.3631x over previous
#include <cuda_runtime.h>
#include <cuda_bf16.h>

typedef unsigned int u32;
typedef unsigned short u16;

// ------------------------- scratch -------------------------
__device__ u16 g_xh[8192 * 512];
__device__ u16 g_xl[8192 * 512];
__device__ u16 g_wth[24 * 64 * 512];   // [wh][n=dh][k=d] transposed
__device__ u16 g_wtl[24 * 64 * 512];
__device__ u16 g_qh[32 * 2048 * 64];   // [bh][s][dh]
__device__ u16 g_ql[32 * 2048 * 64];
__device__ u16 g_kh[32 * 2048 * 64];
__device__ u16 g_kl[32 * 2048 * 64];
__device__ u16 g_vth[32 * 64 * 2048];  // [bh][dh][s] transposed
__device__ u16 g_vtl[32 * 64 * 2048];

// ------------------------- helpers -------------------------
__device__ __forceinline__ float ex2f(float x) {
    float y;
    asm("ex2.approx.f32 %0, %1;" : "=f"(y) : "f"(x));
    return y;
}
// pack (f0,f1): hi = bf16x2{lower=f0, upper=f1}, lo = residuals
__device__ __forceinline__ void split2(float f0, float f1, u32& hi, u32& lo) {
    asm("cvt.rn.bf16x2.f32 %0, %1, %2;" : "=r"(hi) : "f"(f1), "f"(f0));
    float h0 = __uint_as_float(hi << 16);
    float h1 = __uint_as_float(hi & 0xffff0000u);
    asm("cvt.rn.bf16x2.f32 %0, %1, %2;" : "=r"(lo) : "f"(f1 - h1), "f"(f0 - h0));
}
__device__ __forceinline__ void mma16816(float* c,
                                         u32 a0, u32 a1, u32 a2, u32 a3,
                                         u32 b0, u32 b1) {
    asm volatile(
        "mma.sync.aligned.m16n8k16.row.col.f32.bf16.bf16.f32 "
        "{%0,%1,%2,%3}, {%4,%5,%6,%7}, {%8,%9}, {%0,%1,%2,%3};"
        : "+f"(c[0]), "+f"(c[1]), "+f"(c[2]), "+f"(c[3])
        : "r"(a0), "r"(a1), "r"(a2), "r"(a3), "r"(b0), "r"(b1));
}

// ------------------------- prep: split X -------------------------
__global__ __launch_bounds__(256) void split_x_kernel(const float* __restrict__ x) {
    int n4 = 8192 * 512 / 4;
    for (int i = blockIdx.x * 256 + threadIdx.x; i < n4; i += gridDim.x * 256) {
        float4 v = ((const float4*)x)[i];
        u32 h0, l0, h1, l1;
        split2(v.x, v.y, h0, l0);
        split2(v.z, v.w, h1, l1);
        ((uint2*)g_xh)[i] = make_uint2(h0, h1);
        ((uint2*)g_xl)[i] = make_uint2(l0, l1);
    }
}

// ------------------------- prep: transpose + split W -------------------------
__global__ __launch_bounds__(256) void split_w_kernel(
    const float* __restrict__ Wq, const float* __restrict__ Wk, const float* __restrict__ Wv) {
    __shared__ float tile[64][65];
    int wh = blockIdx.x, w = wh >> 3, h = wh & 7, t = threadIdx.x;
    const float* W = (w == 0 ? Wq : (w == 1 ? Wk : Wv)) + h * 512 * 64;
    float c = (w == 0) ? 0.125f * 1.4426950408889634f : 1.0f;  // fold scale*log2(e) into Wq
    for (int k0 = 0; k0 < 512; k0 += 64) {
        __syncthreads();
        for (int e = t; e < 4096; e += 256)
            tile[e >> 6][e & 63] = W[(k0 + (e >> 6)) * 64 + (e & 63)] * c;
        __syncthreads();
        for (int e = t; e < 4096; e += 256) {
            int n = e >> 6, kk = e & 63;
            float f = tile[kk][n];
            __nv_bfloat16 hb = __float2bfloat16(f);
            int o = (wh * 64 + n) * 512 + k0 + kk;
            g_wth[o] = *(u16*)&hb;
            __nv_bfloat16 lb = __float2bfloat16(f - __bfloat162float(hb));
            g_wtl[o] = *(u16*)&lb;
        }
    }
}

// --------------------------- QKV projection (HMMA) ---------------------------
// grid (64, 8): 128-row M tile x head. N=192 (Q|K|V), K=512 in 8 chunks of 64.
#define QK_SMEM ((2 * 128 * 72 + 2 * 192 * 72) * 2)

__global__ __launch_bounds__(256) void qkv_mma_kernel() {
    extern __shared__ u16 sm[];
    u16* Xh = sm;                      // [128][72]
    u16* Xl = sm + 128 * 72;
    u16* Wh = sm + 2 * 128 * 72;       // [192][72]
    u16* Wl = sm + 2 * 128 * 72 + 192 * 72;

    int t = threadIdx.x, w = t >> 5, lane = t & 31;
    int g = lane >> 2, tg = lane & 3;
    int m0 = blockIdx.x * 128, h = blockIdx.y;

    float acc[24][4];
    #pragma unroll
    for (int n = 0; n < 24; n++)
        #pragma unroll
        for (int e = 0; e < 4; e++) acc[n][e] = 0.0f;

    for (int kb = 0; kb < 8; kb++) {
        int k0 = kb * 64;
        __syncthreads();
        for (int e = t; e < 1024; e += 256) {
            int r = e >> 3, u = e & 7;
            *(uint4*)(Xh + r * 72 + u * 8) = *(const uint4*)(g_xh + (m0 + r) * 512 + k0 + u * 8);
            *(uint4*)(Xl + r * 72 + u * 8) = *(const uint4*)(g_xl + (m0 + r) * 512 + k0 + u * 8);
        }
        for (int e = t; e < 1536; e += 256) {
            int r = e >> 3, u = e & 7;
            int src = (((r >> 6) * 8 + h) * 64 + (r & 63)) * 512 + k0 + u * 8;
            *(uint4*)(Wh + r * 72 + u * 8) = *(const uint4*)(g_wth + src);
            *(uint4*)(Wl + r * 72 + u * 8) = *(const uint4*)(g_wtl + src);
        }
        __syncthreads();

        #pragma unroll
        for (int kc = 0; kc < 4; kc++) {
            const u16* x0 = Xh + (w * 16 + g) * 72 + kc * 16 + 2 * tg;
            const u16* y0 = Xl + (w * 16 + g) * 72 + kc * 16 + 2 * tg;
            u32 ah0 = *(const u32*)x0,            ah1 = *(const u32*)(x0 + 8 * 72);
            u32 ah2 = *(const u32*)(x0 + 8),      ah3 = *(const u32*)(x0 + 8 * 72 + 8);
            u32 al0 = *(const u32*)y0,            al1 = *(const u32*)(y0 + 8 * 72);
            u32 al2 = *(const u32*)(y0 + 8),      al3 = *(const u32*)(y0 + 8 * 72 + 8);
            // term-outer: consecutive MMAs hit 24 independent accumulators
            #pragma unroll
            for (int term = 0; term < 3; term++) {
                #pragma unroll
                for (int nt = 0; nt < 24; nt++) {
                    const u16* bp = (term == 2 ? Wl : Wh) + (nt * 8 + g) * 72 + kc * 16 + 2 * tg;
                    u32 b0 = *(const u32*)bp, b1 = *(const u32*)(bp + 8);
                    if (term == 1) mma16816(acc[nt], al0, al1, al2, al3, b0, b1);
                    else           mma16816(acc[nt], ah0, ah1, ah2, ah3, b0, b1);
                }
            }
        }
    }

    // epilogue: rows m (c0,c1) and m+8 (c2,c3)
    int m = m0 + w * 16 + g;
    int b = m >> 11, s = m & 2047, bh = b * 8 + h;
    #pragma unroll
    for (int wi = 0; wi < 3; wi++) {
        #pragma unroll
        for (int ntl = 0; ntl < 8; ntl++) {
            float c0 = acc[wi * 8 + ntl][0], c1 = acc[wi * 8 + ntl][1];
            float c2 = acc[wi * 8 + ntl][2], c3 = acc[wi * 8 + ntl][3];
            if (wi < 2) {
                u32* oh = (u32*)(wi == 0 ? g_qh : g_kh);
                u32* ol = (u32*)(wi == 0 ? g_ql : g_kl);
                u32 hw, lw;
                split2(c0, c1, hw, lw);
                int i0 = (bh * 2048 + s) * 32 + ntl * 4 + tg;
                oh[i0] = hw; ol[i0] = lw;
                split2(c2, c3, hw, lw);
                int i1 = i0 + 8 * 32;
                oh[i1] = hw; ol[i1] = lw;
            } else {
                int d0 = ntl * 8 + 2 * tg;
                float cv[4] = {c0, c1, c2, c3};
                #pragma unroll
                for (int e = 0; e < 4; e++) {
                    int d = d0 + (e & 1), ss = s + (e >> 1) * 8;
                    __nv_bfloat16 hb = __float2bfloat16(cv[e]);
                    __nv_bfloat16 lb = __float2bfloat16(cv[e] - __bfloat162float(hb));
                    g_vth[(bh * 64 + d) * 2048 + ss] = *(u16*)&hb;
                    g_vtl[(bh * 64 + d) * 2048 + ss] = *(u16*)&lb;
                }
            }
        }
    }
}

// ----------------------------- attention (HMMA) -----------------------------
// grid (16, 32). 8 warps; warp w owns 16 query rows. 16 KV tiles of 128.
// No-max softmax; O accumulates in registers. 2 CTAs/SM (reg cap 128).
#define AT_SMEM ((2 * 128 * 72 + 2 * 128 * 72 + 2 * 64 * 136) * 2)

__global__ __launch_bounds__(256, 2) void attn_mma_kernel(float* __restrict__ out) {
    extern __shared__ u16 sm[];
    u16* Qh = sm;                        // [128][72]
    u16* Ql = sm + 128 * 72;
    u16* Kh = sm + 2 * 128 * 72;         // [128][72]
    u16* Kl = sm + 3 * 128 * 72;
    u16* Vh = sm + 4 * 128 * 72;         // [64][136]  (V^T: [d][kv])
    u16* Vl = sm + 4 * 128 * 72 + 64 * 136;

    int t = threadIdx.x, w = t >> 5, lane = t & 31;
    int g = lane >> 2, tg = lane & 3;
    int q0 = blockIdx.x * 128, bh = blockIdx.y;

    // load Q tile (hi/lo)
    for (int e = t; e < 1024; e += 256) {
        int r = e >> 3, u = e & 7;
        int src = (bh * 2048 + q0 + r) * 64 + u * 8;
        *(uint4*)(Qh + r * 72 + u * 8) = *(const uint4*)(g_qh + src);
        *(uint4*)(Ql + r * 72 + u * 8) = *(const uint4*)(g_ql + src);
    }
    __syncthreads();

    // preload Q A-fragments (held in registers across all tiles)
    u32 qah[4][4], qal[4][4];
    #pragma unroll
    for (int kc = 0; kc < 4; kc++) {
        const u16* x0 = Qh + (w * 16 + g) * 72 + kc * 16 + 2 * tg;
        const u16* y0 = Ql + (w * 16 + g) * 72 + kc * 16 + 2 * tg;
        qah[kc][0] = *(const u32*)x0;        qah[kc][1] = *(const u32*)(x0 + 8 * 72);
        qah[kc][2] = *(const u32*)(x0 + 8);  qah[kc][3] = *(const u32*)(x0 + 8 * 72 + 8);
        qal[kc][0] = *(const u32*)y0;        qal[kc][1] = *(const u32*)(y0 + 8 * 72);
        qal[kc][2] = *(const u32*)(y0 + 8);  qal[kc][3] = *(const u32*)(y0 + 8 * 72 + 8);
    }

    float oacc[8][4];
    #pragma unroll
    for (int n = 0; n < 8; n++)
        #pragma unroll
        for (int e = 0; e < 4; e++) oacc[n][e] = 0.0f;
    float l0 = 0.0f, l1 = 0.0f;

    for (int kt = 0; kt < 16; kt++) {
        int s0 = kt * 128;
        __syncthreads();
        for (int e = t; e < 1024; e += 256) {
            int r = e >> 3, u = e & 7;
            int src = (bh * 2048 + s0 + r) * 64 + u * 8;
            *(uint4*)(Kh + r * 72 + u * 8) = *(const uint4*)(g_kh + src);
            *(uint4*)(Kl + r * 72 + u * 8) = *(const uint4*)(g_kl + src);
        }
        for (int e = t; e < 1024; e += 256) {
            int d = e >> 4, u = e & 15;
            int src = (bh * 64 + d) * 2048 + s0 + u * 8;
            *(uint4*)(Vh + d * 136 + u * 8) = *(const uint4*)(g_vth + src);
            *(uint4*)(Vl + d * 136 + u * 8) = *(const uint4*)(g_vtl + src);
        }
        __syncthreads();

        #pragma unroll
        for (int half = 0; half < 2; half++) {
            // S = Q K^T for kv columns [half*64, half*64+64)
            float sacc[8][4];
            #pragma unroll
            for (int n = 0; n < 8; n++)
                #pragma unroll
                for (int e = 0; e < 4; e++) sacc[n][e] = 0.0f;

            // term-outer: 8 independent accumulator chains
            #pragma unroll
            for (int term = 0; term < 3; term++) {
                #pragma unroll
                for (int kc = 0; kc < 4; kc++) {
                    #pragma unroll
                    for (int nt = 0; nt < 8; nt++) {
                        int kvrow = (half * 8 + nt) * 8 + g;
                        const u16* bp = (term == 2 ? Kl : Kh) + kvrow * 72 + kc * 16 + 2 * tg;
                        u32 b0 = *(const u32*)bp, b1 = *(const u32*)(bp + 8);
                        if (term == 1)
                            mma16816(sacc[nt], qal[kc][0], qal[kc][1], qal[kc][2], qal[kc][3], b0, b1);
                        else
                            mma16816(sacc[nt], qah[kc][0], qah[kc][1], qah[kc][2], qah[kc][3], b0, b1);
                    }
                }
            }
            // softmax numerators (scores already * log2e): p = 2^s
            #pragma unroll
            for (int nt = 0; nt < 8; nt++) {
                sacc[nt][0] = ex2f(sacc[nt][0]);
                sacc[nt][1] = ex2f(sacc[nt][1]);
                sacc[nt][2] = ex2f(sacc[nt][2]);
                sacc[nt][3] = ex2f(sacc[nt][3]);
                l0 += sacc[nt][0] + sacc[nt][1];
                l1 += sacc[nt][2] + sacc[nt][3];
            }
            // O += P V  (P reused from registers as A fragments)
            #pragma unroll
            for (int c = 0; c < 4; c++) {
                u32 ah0, al0, ah1, al1, ah2, al2, ah3, al3;
                split2(sacc[2 * c][0],     sacc[2 * c][1],     ah0, al0);
                split2(sacc[2 * c][2],     sacc[2 * c][3],     ah1, al1);
                split2(sacc[2 * c + 1][0], sacc[2 * c + 1][1], ah2, al2);
                split2(sacc[2 * c + 1][2], sacc[2 * c + 1][3], ah3, al3);
                int col = half * 64 + c * 16 + 2 * tg;
                // term-outer: 8 independent chains over dt
                #pragma unroll
                for (int term = 0; term < 3; term++) {
                    #pragma unroll
                    for (int dt = 0; dt < 8; dt++) {
                        const u16* bp = (term == 2 ? Vl : Vh) + (dt * 8 + g) * 136 + col;
                        u32 b0 = *(const u32*)bp, b1 = *(const u32*)(bp + 8);
                        if (term == 1) mma16816(oacc[dt], al0, al1, al2, al3, b0, b1);
                        else           mma16816(oacc[dt], ah0, ah1, ah2, ah3, b0, b1);
                    }
                }
            }
        }
    }

    // row-sum reduce across the 4 threads of each row group
    l0 += __shfl_xor_sync(0xffffffffu, l0, 1);
    l0 += __shfl_xor_sync(0xffffffffu, l0, 2);
    l1 += __shfl_xor_sync(0xffffffffu, l1, 1);
    l1 += __shfl_xor_sync(0xffffffffu, l1, 2);
    float inv0 = 1.0f / l0, inv1 = 1.0f / l1;

    int b = bh >> 3, h = bh & 7;
    int s = q0 + w * 16 + g;
    float* o0 = out + ((b * 2048 + s) * 8 + h) * 64;
    float* o1 = out + ((b * 2048 + s + 8) * 8 + h) * 64;
    #pragma unroll
    for (int dt = 0; dt < 8; dt++) {
        *(float2*)(o0 + dt * 8 + 2 * tg) = make_float2(oacc[dt][0] * inv0, oacc[dt][1] * inv0);
        *(float2*)(o1 + dt * 8 + 2 * tg) = make_float2(oacc[dt][2] * inv1, oacc[dt][3] * inv1);
    }
}

extern "C" void kernel_launch(void* const* d_in, const int* in_sizes, int n_in,
                              void* d_out, int out_size)
{
    const float* x  = (const float*)d_in[0];
    const float* Wq = (const float*)d_in[1];
    const float* Wk = (const float*)d_in[2];
    const float* Wv = (const float*)d_in[3];
    float* out = (float*)d_out;

    cudaFuncSetAttribute(qkv_mma_kernel,  cudaFuncAttributeMaxDynamicSharedMemorySize, QK_SMEM);
    cudaFuncSetAttribute(attn_mma_kernel, cudaFuncAttributeMaxDynamicSharedMemorySize, AT_SMEM);

    split_x_kernel<<<512, 256>>>(x);
    split_w_kernel<<<24, 256>>>(Wq, Wk, Wv);
    qkv_mma_kernel<<<dim3(64, 8), 256, QK_SMEM>>>();
    attn_mma_kernel<<<dim3(16, 32), 256, AT_SMEM>>>(out);
}

// round 8
// speedup vs baseline: 4.2817x; 1.0238x over previous
#include <cuda_runtime.h>
#include <cuda_bf16.h>

typedef unsigned int u32;
typedef unsigned short u16;

// ------------------------- scratch -------------------------
__device__ u16 g_xh[8192 * 512];
__device__ u16 g_xl[8192 * 512];
__device__ u16 g_wth[24 * 64 * 512];   // [wh][n=dh][k=d] transposed
__device__ u16 g_wtl[24 * 64 * 512];
__device__ u16 g_qh[32 * 2048 * 64];   // [bh][s][dh]
__device__ u16 g_ql[32 * 2048 * 64];
__device__ u16 g_kh[32 * 2048 * 64];
__device__ u16 g_kl[32 * 2048 * 64];
__device__ u16 g_vth[32 * 64 * 2048];  // [bh][dh][s] transposed
__device__ u16 g_vtl[32 * 64 * 2048];

// ------------------------- helpers -------------------------
__device__ __forceinline__ float ex2f(float x) {
    float y;
    asm("ex2.approx.f32 %0, %1;" : "=f"(y) : "f"(x));
    return y;
}
__device__ __forceinline__ void split2(float f0, float f1, u32& hi, u32& lo) {
    asm("cvt.rn.bf16x2.f32 %0, %1, %2;" : "=r"(hi) : "f"(f1), "f"(f0));
    float h0 = __uint_as_float(hi << 16);
    float h1 = __uint_as_float(hi & 0xffff0000u);
    asm("cvt.rn.bf16x2.f32 %0, %1, %2;" : "=r"(lo) : "f"(f1 - h1), "f"(f0 - h0));
}
__device__ __forceinline__ void mma16816(float* c, const u32* a, u32 b0, u32 b1) {
    asm volatile(
        "mma.sync.aligned.m16n8k16.row.col.f32.bf16.bf16.f32 "
        "{%0,%1,%2,%3}, {%4,%5,%6,%7}, {%8,%9}, {%0,%1,%2,%3};"
        : "+f"(c[0]), "+f"(c[1]), "+f"(c[2]), "+f"(c[3])
        : "r"(a[0]), "r"(a[1]), "r"(a[2]), "r"(a[3]), "r"(b0), "r"(b1));
}
__device__ __forceinline__ void ldmx4(u32* r, u32 saddr) {
    asm volatile("ldmatrix.sync.aligned.m8n8.x4.shared.b16 {%0,%1,%2,%3}, [%4];"
        : "=r"(r[0]), "=r"(r[1]), "=r"(r[2]), "=r"(r[3]) : "r"(saddr));
}
__device__ __forceinline__ u32 sm_addr(const void* p) {
    return (u32)__cvta_generic_to_shared(p);
}

// ------------------------- prep: split X -------------------------
__global__ __launch_bounds__(256) void split_x_kernel(const float* __restrict__ x) {
    int n4 = 8192 * 512 / 4;
    for (int i = blockIdx.x * 256 + threadIdx.x; i < n4; i += gridDim.x * 256) {
        float4 v = ((const float4*)x)[i];
        u32 h0, l0, h1, l1;
        split2(v.x, v.y, h0, l0);
        split2(v.z, v.w, h1, l1);
        ((uint2*)g_xh)[i] = make_uint2(h0, h1);
        ((uint2*)g_xl)[i] = make_uint2(l0, l1);
    }
}

// ------------------------- prep: transpose + split W -------------------------
__global__ __launch_bounds__(256) void split_w_kernel(
    const float* __restrict__ Wq, const float* __restrict__ Wk, const float* __restrict__ Wv) {
    __shared__ float tile[64][65];
    int wh = blockIdx.x, w = wh >> 3, h = wh & 7, t = threadIdx.x;
    const float* W = (w == 0 ? Wq : (w == 1 ? Wk : Wv)) + h * 512 * 64;
    float c = (w == 0) ? 0.125f * 1.4426950408889634f : 1.0f;  // fold scale*log2(e) into Wq
    for (int k0 = 0; k0 < 512; k0 += 64) {
        __syncthreads();
        for (int e = t; e < 4096; e += 256)
            tile[e >> 6][e & 63] = W[(k0 + (e >> 6)) * 64 + (e & 63)] * c;
        __syncthreads();
        for (int e = t; e < 4096; e += 256) {
            int n = e >> 6, kk = e & 63;
            float f = tile[kk][n];
            __nv_bfloat16 hb = __float2bfloat16(f);
            int o = (wh * 64 + n) * 512 + k0 + kk;
            g_wth[o] = *(u16*)&hb;
            __nv_bfloat16 lb = __float2bfloat16(f - __bfloat162float(hb));
            g_wtl[o] = *(u16*)&lb;
        }
    }
}

// --------------------------- QKV projection (HMMA + ldmatrix) ---------------------------
// grid (64, 24): 128-row M tile x (weight*8+head). N=64, K=512 in 8 chunks of 64.
#define QK_SMEM ((2 * 128 * 72 + 2 * 64 * 72) * 2)

__global__ __launch_bounds__(256, 2) void qkv_mma_kernel() {
    extern __shared__ u16 sm[];
    u16* Xh = sm;                      // [128][72]
    u16* Xl = sm + 128 * 72;
    u16* Wh = sm + 2 * 128 * 72;       // [64][72]
    u16* Wl = sm + 2 * 128 * 72 + 64 * 72;

    int t = threadIdx.x, w = t >> 5, lane = t & 31;
    int g = lane >> 2, tg = lane & 3;
    int m0 = blockIdx.x * 128, wh = blockIdx.y;

    // per-thread ldmatrix offsets (bytes)
    u32 XhS = sm_addr(Xh), XlS = sm_addr(Xl), WhS = sm_addr(Wh), WlS = sm_addr(Wl);
    u32 aOff = (u32)((w * 16 + ((lane >> 3) & 1) * 8 + (lane & 7)) * 144 + (lane >> 4) * 16);
    u32 bOff = (u32)((lane & 7) * 144 + (lane >> 3) * 16);

    float acc[8][4];
    #pragma unroll
    for (int n = 0; n < 8; n++)
        #pragma unroll
        for (int e = 0; e < 4; e++) acc[n][e] = 0.0f;

    for (int kb = 0; kb < 8; kb++) {
        int k0 = kb * 64;
        __syncthreads();
        for (int e = t; e < 1024; e += 256) {
            int r = e >> 3, u = e & 7;
            *(uint4*)(Xh + r * 72 + u * 8) = *(const uint4*)(g_xh + (m0 + r) * 512 + k0 + u * 8);
            *(uint4*)(Xl + r * 72 + u * 8) = *(const uint4*)(g_xl + (m0 + r) * 512 + k0 + u * 8);
        }
        for (int e = t; e < 512; e += 256) {
            int r = e >> 3, u = e & 7;
            int src = (wh * 64 + r) * 512 + k0 + u * 8;
            *(uint4*)(Wh + r * 72 + u * 8) = *(const uint4*)(g_wth + src);
            *(uint4*)(Wl + r * 72 + u * 8) = *(const uint4*)(g_wtl + src);
        }
        __syncthreads();

        #pragma unroll
        for (int kc2 = 0; kc2 < 2; kc2++) {
            u32 ah[2][4], al[2][4];
            ldmx4(ah[0], XhS + aOff + kc2 * 64);
            ldmx4(ah[1], XhS + aOff + kc2 * 64 + 32);
            ldmx4(al[0], XlS + aOff + kc2 * 64);
            ldmx4(al[1], XlS + aOff + kc2 * 64 + 32);
            #pragma unroll
            for (int ntg = 0; ntg < 2; ntg++) {
                u32 bf[4][4];
                #pragma unroll
                for (int j = 0; j < 4; j++)
                    ldmx4(bf[j], WhS + bOff + (ntg * 4 + j) * 8 * 144 + kc2 * 64);
                #pragma unroll
                for (int j = 0; j < 4; j++) mma16816(acc[ntg * 4 + j], ah[0], bf[j][0], bf[j][1]);
                #pragma unroll
                for (int j = 0; j < 4; j++) mma16816(acc[ntg * 4 + j], ah[1], bf[j][2], bf[j][3]);
                #pragma unroll
                for (int j = 0; j < 4; j++) mma16816(acc[ntg * 4 + j], al[0], bf[j][0], bf[j][1]);
                #pragma unroll
                for (int j = 0; j < 4; j++) mma16816(acc[ntg * 4 + j], al[1], bf[j][2], bf[j][3]);
                #pragma unroll
                for (int j = 0; j < 4; j++)
                    ldmx4(bf[j], WlS + bOff + (ntg * 4 + j) * 8 * 144 + kc2 * 64);
                #pragma unroll
                for (int j = 0; j < 4; j++) mma16816(acc[ntg * 4 + j], ah[0], bf[j][0], bf[j][1]);
                #pragma unroll
                for (int j = 0; j < 4; j++) mma16816(acc[ntg * 4 + j], ah[1], bf[j][2], bf[j][3]);
            }
        }
    }

    // epilogue
    int m = m0 + w * 16 + g;
    int b = m >> 11, s = m & 2047;
    int wi = wh >> 3, h = wh & 7, bh = b * 8 + h;
    #pragma unroll
    for (int ntl = 0; ntl < 8; ntl++) {
        float c0 = acc[ntl][0], c1 = acc[ntl][1], c2 = acc[ntl][2], c3 = acc[ntl][3];
        if (wi < 2) {
            u32* oh = (u32*)(wi == 0 ? g_qh : g_kh);
            u32* ol = (u32*)(wi == 0 ? g_ql : g_kl);
            u32 hw, lw;
            split2(c0, c1, hw, lw);
            int i0 = (bh * 2048 + s) * 32 + ntl * 4 + tg;
            oh[i0] = hw; ol[i0] = lw;
            split2(c2, c3, hw, lw);
            int i1 = i0 + 8 * 32;
            oh[i1] = hw; ol[i1] = lw;
        } else {
            int d0 = ntl * 8 + 2 * tg;
            float cv[4] = {c0, c1, c2, c3};
            #pragma unroll
            for (int e = 0; e < 4; e++) {
                int d = d0 + (e & 1), ss = s + (e >> 1) * 8;
                __nv_bfloat16 hb = __float2bfloat16(cv[e]);
                __nv_bfloat16 lb = __float2bfloat16(cv[e] - __bfloat162float(hb));
                g_vth[(bh * 64 + d) * 2048 + ss] = *(u16*)&hb;
                g_vtl[(bh * 64 + d) * 2048 + ss] = *(u16*)&lb;
            }
        }
    }
}

// ----------------------------- attention (HMMA + ldmatrix) -----------------------------
// grid (16, 32). 8 warps x 16 query rows. 16 KV tiles of 128. No-max softmax.
#define AT_SMEM ((2 * 128 * 72 + 2 * 128 * 72 + 2 * 64 * 136) * 2)

__global__ __launch_bounds__(256, 2) void attn_mma_kernel(float* __restrict__ out) {
    extern __shared__ u16 sm[];
    u16* Qh = sm;                        // [128][72]
    u16* Ql = sm + 128 * 72;
    u16* Kh = sm + 2 * 128 * 72;         // [128][72]
    u16* Kl = sm + 3 * 128 * 72;
    u16* Vh = sm + 4 * 128 * 72;         // [64][136]  (V^T: [d][kv])
    u16* Vl = sm + 4 * 128 * 72 + 64 * 136;

    int t = threadIdx.x, w = t >> 5, lane = t & 31;
    int g = lane >> 2, tg = lane & 3;
    int q0 = blockIdx.x * 128, bh = blockIdx.y;

    u32 QhS = sm_addr(Qh), QlS = sm_addr(Ql);
    u32 KhS = sm_addr(Kh), KlS = sm_addr(Kl);
    u32 VhS = sm_addr(Vh), VlS = sm_addr(Vl);
    u32 aOff = (u32)((w * 16 + ((lane >> 3) & 1) * 8 + (lane & 7)) * 144 + (lane >> 4) * 16);
    u32 kOff = (u32)((lane & 7) * 144 + (lane >> 3) * 16);
    u32 vOff = (u32)((lane & 7) * 272 + (lane >> 3) * 16);

    // load Q tile (hi/lo)
    for (int e = t; e < 1024; e += 256) {
        int r = e >> 3, u = e & 7;
        int src = (bh * 2048 + q0 + r) * 64 + u * 8;
        *(uint4*)(Qh + r * 72 + u * 8) = *(const uint4*)(g_qh + src);
        *(uint4*)(Ql + r * 72 + u * 8) = *(const uint4*)(g_ql + src);
    }
    __syncthreads();

    // resident Q-hi fragments (Q-lo loaded on the fly from smem)
    u32 qah[4][4];
    #pragma unroll
    for (int kc = 0; kc < 4; kc++) ldmx4(qah[kc], QhS + aOff + kc * 32);

    float oacc[8][4];
    #pragma unroll
    for (int n = 0; n < 8; n++)
        #pragma unroll
        for (int e = 0; e < 4; e++) oacc[n][e] = 0.0f;
    float l0 = 0.0f, l1 = 0.0f;

    for (int kt = 0; kt < 16; kt++) {
        int s0 = kt * 128;
        __syncthreads();
        for (int e = t; e < 1024; e += 256) {
            int r = e >> 3, u = e & 7;
            int src = (bh * 2048 + s0 + r) * 64 + u * 8;
            *(uint4*)(Kh + r * 72 + u * 8) = *(const uint4*)(g_kh + src);
            *(uint4*)(Kl + r * 72 + u * 8) = *(const uint4*)(g_kl + src);
        }
        for (int e = t; e < 1024; e += 256) {
            int d = e >> 4, u = e & 15;
            int src = (bh * 64 + d) * 2048 + s0 + u * 8;
            *(uint4*)(Vh + d * 136 + u * 8) = *(const uint4*)(g_vth + src);
            *(uint4*)(Vl + d * 136 + u * 8) = *(const uint4*)(g_vtl + src);
        }
        __syncthreads();

        #pragma unroll
        for (int half = 0; half < 2; half++) {
            // ---- S = Q K^T for kv columns [half*64, half*64+64) ----
            float sacc[8][4];
            #pragma unroll
            for (int n = 0; n < 8; n++)
                #pragma unroll
                for (int e = 0; e < 4; e++) sacc[n][e] = 0.0f;

            #pragma unroll
            for (int kc2 = 0; kc2 < 2; kc2++) {
                u32 qal[2][4];
                ldmx4(qal[0], QlS + aOff + kc2 * 64);
                ldmx4(qal[1], QlS + aOff + kc2 * 64 + 32);
                #pragma unroll
                for (int ntg = 0; ntg < 2; ntg++) {
                    u32 bf[4][4];
                    #pragma unroll
                    for (int j = 0; j < 4; j++)
                        ldmx4(bf[j], KhS + kOff + (half * 64 + (ntg * 4 + j) * 8) * 144 + kc2 * 64);
                    #pragma unroll
                    for (int j = 0; j < 4; j++) mma16816(sacc[ntg * 4 + j], qah[2 * kc2],     bf[j][0], bf[j][1]);
                    #pragma unroll
                    for (int j = 0; j < 4; j++) mma16816(sacc[ntg * 4 + j], qah[2 * kc2 + 1], bf[j][2], bf[j][3]);
                    #pragma unroll
                    for (int j = 0; j < 4; j++) mma16816(sacc[ntg * 4 + j], qal[0], bf[j][0], bf[j][1]);
                    #pragma unroll
                    for (int j = 0; j < 4; j++) mma16816(sacc[ntg * 4 + j], qal[1], bf[j][2], bf[j][3]);
                    #pragma unroll
                    for (int j = 0; j < 4; j++)
                        ldmx4(bf[j], KlS + kOff + (half * 64 + (ntg * 4 + j) * 8) * 144 + kc2 * 64);
                    #pragma unroll
                    for (int j = 0; j < 4; j++) mma16816(sacc[ntg * 4 + j], qah[2 * kc2],     bf[j][0], bf[j][1]);
                    #pragma unroll
                    for (int j = 0; j < 4; j++) mma16816(sacc[ntg * 4 + j], qah[2 * kc2 + 1], bf[j][2], bf[j][3]);
                }
            }

            // ---- softmax numerators: p = 2^s (scores pre-scaled by log2e) ----
            #pragma unroll
            for (int nt = 0; nt < 8; nt++) {
                sacc[nt][0] = ex2f(sacc[nt][0]);
                sacc[nt][1] = ex2f(sacc[nt][1]);
                sacc[nt][2] = ex2f(sacc[nt][2]);
                sacc[nt][3] = ex2f(sacc[nt][3]);
                l0 += sacc[nt][0] + sacc[nt][1];
                l1 += sacc[nt][2] + sacc[nt][3];
            }

            // ---- O += P V ----
            #pragma unroll
            for (int c2 = 0; c2 < 2; c2++) {
                u32 pah[2][4], pal[2][4];
                #pragma unroll
                for (int cc = 0; cc < 2; cc++) {
                    int c = 2 * c2 + cc;
                    split2(sacc[2 * c][0],     sacc[2 * c][1],     pah[cc][0], pal[cc][0]);
                    split2(sacc[2 * c][2],     sacc[2 * c][3],     pah[cc][1], pal[cc][1]);
                    split2(sacc[2 * c + 1][0], sacc[2 * c + 1][1], pah[cc][2], pal[cc][2]);
                    split2(sacc[2 * c + 1][2], sacc[2 * c + 1][3], pah[cc][3], pal[cc][3]);
                }
                #pragma unroll
                for (int dtg = 0; dtg < 2; dtg++) {
                    u32 vf[4][4];
                    #pragma unroll
                    for (int j = 0; j < 4; j++)
                        ldmx4(vf[j], VhS + vOff + (dtg * 4 + j) * 8 * 272 + half * 128 + c2 * 64);
                    #pragma unroll
                    for (int j = 0; j < 4; j++) mma16816(oacc[dtg * 4 + j], pah[0], vf[j][0], vf[j][1]);
                    #pragma unroll
                    for (int j = 0; j < 4; j++) mma16816(oacc[dtg * 4 + j], pah[1], vf[j][2], vf[j][3]);
                    #pragma unroll
                    for (int j = 0; j < 4; j++) mma16816(oacc[dtg * 4 + j], pal[0], vf[j][0], vf[j][1]);
                    #pragma unroll
                    for (int j = 0; j < 4; j++) mma16816(oacc[dtg * 4 + j], pal[1], vf[j][2], vf[j][3]);
                    #pragma unroll
                    for (int j = 0; j < 4; j++)
                        ldmx4(vf[j], VlS + vOff + (dtg * 4 + j) * 8 * 272 + half * 128 + c2 * 64);
                    #pragma unroll
                    for (int j = 0; j < 4; j++) mma16816(oacc[dtg * 4 + j], pah[0], vf[j][0], vf[j][1]);
                    #pragma unroll
                    for (int j = 0; j < 4; j++) mma16816(oacc[dtg * 4 + j], pah[1], vf[j][2], vf[j][3]);
                }
            }
        }
    }

    // row-sum reduce across the 4 threads of each row group
    l0 += __shfl_xor_sync(0xffffffffu, l0, 1);
    l0 += __shfl_xor_sync(0xffffffffu, l0, 2);
    l1 += __shfl_xor_sync(0xffffffffu, l1, 1);
    l1 += __shfl_xor_sync(0xffffffffu, l1, 2);
    float inv0 = 1.0f / l0, inv1 = 1.0f / l1;

    int b = bh >> 3, h = bh & 7;
    int s = q0 + w * 16 + g;
    float* o0 = out + ((b * 2048 + s) * 8 + h) * 64;
    float* o1 = out + ((b * 2048 + s + 8) * 8 + h) * 64;
    #pragma unroll
    for (int dt = 0; dt < 8; dt++) {
        *(float2*)(o0 + dt * 8 + 2 * tg) = make_float2(oacc[dt][0] * inv0, oacc[dt][1] * inv0);
        *(float2*)(o1 + dt * 8 + 2 * tg) = make_float2(oacc[dt][2] * inv1, oacc[dt][3] * inv1);
    }
}

extern "C" void kernel_launch(void* const* d_in, const int* in_sizes, int n_in,
                              void* d_out, int out_size)
{
    const float* x  = (const float*)d_in[0];
    const float* Wq = (const float*)d_in[1];
    const float* Wk = (const float*)d_in[2];
    const float* Wv = (const float*)d_in[3];
    float* out = (float*)d_out;

    cudaFuncSetAttribute(qkv_mma_kernel,  cudaFuncAttributeMaxDynamicSharedMemorySize, QK_SMEM);
    cudaFuncSetAttribute(attn_mma_kernel, cudaFuncAttributeMaxDynamicSharedMemorySize, AT_SMEM);

    split_x_kernel<<<512, 256>>>(x);
    split_w_kernel<<<24, 256>>>(Wq, Wk, Wv);
    qkv_mma_kernel<<<dim3(64, 24), 256, QK_SMEM>>>();
    attn_mma_kernel<<<dim3(16, 32), 256, AT_SMEM>>>(out);
}

// round 10
// speedup vs baseline: 4.9091x; 1.1465x over previous
#include <cuda_runtime.h>
#include <cuda_bf16.h>

typedef unsigned int u32;
typedef unsigned short u16;

// ------------------------- scratch -------------------------
__device__ u16 g_xh[8192 * 512];
__device__ u16 g_xl[8192 * 512];
__device__ u16 g_wth[24 * 64 * 512];   // [wh][n=dh][k=d] transposed
__device__ u16 g_wtl[24 * 64 * 512];
__device__ u16 g_qh[32 * 2048 * 64];   // [bh][s][dh]
__device__ u16 g_ql[32 * 2048 * 64];
__device__ u16 g_kh[32 * 2048 * 64];
__device__ u16 g_kl[32 * 2048 * 64];
__device__ u16 g_vth[32 * 64 * 2048];  // [bh][dh][s] transposed
__device__ u16 g_vtl[32 * 64 * 2048];

// ------------------------- helpers -------------------------
__device__ __forceinline__ float ex2f(float x) {
    float y;
    asm("ex2.approx.f32 %0, %1;" : "=f"(y) : "f"(x));
    return y;
}
__device__ __forceinline__ void split2(float f0, float f1, u32& hi, u32& lo) {
    asm("cvt.rn.bf16x2.f32 %0, %1, %2;" : "=r"(hi) : "f"(f1), "f"(f0));
    float h0 = __uint_as_float(hi << 16);
    float h1 = __uint_as_float(hi & 0xffff0000u);
    asm("cvt.rn.bf16x2.f32 %0, %1, %2;" : "=r"(lo) : "f"(f1 - h1), "f"(f0 - h0));
}
__device__ __forceinline__ void mma16816(float* c, const u32* a, u32 b0, u32 b1) {
    asm volatile(
        "mma.sync.aligned.m16n8k16.row.col.f32.bf16.bf16.f32 "
        "{%0,%1,%2,%3}, {%4,%5,%6,%7}, {%8,%9}, {%0,%1,%2,%3};"
        : "+f"(c[0]), "+f"(c[1]), "+f"(c[2]), "+f"(c[3])
        : "r"(a[0]), "r"(a[1]), "r"(a[2]), "r"(a[3]), "r"(b0), "r"(b1));
}
__device__ __forceinline__ void ldmx4(u32* r, u32 saddr) {
    asm volatile("ldmatrix.sync.aligned.m8n8.x4.shared.b16 {%0,%1,%2,%3}, [%4];"
        : "=r"(r[0]), "=r"(r[1]), "=r"(r[2]), "=r"(r[3]) : "r"(saddr));
}
__device__ __forceinline__ u32 sm_addr(const void* p) {
    return (u32)__cvta_generic_to_shared(p);
}
#define CP16(smB, gp)  asm volatile("cp.async.cg.shared.global [%0], [%1], 16;" :: "r"(smB), "l"(gp) : "memory")
#define CPCOMMIT()     asm volatile("cp.async.commit_group;" ::: "memory")
#define CPWAIT0()      asm volatile("cp.async.wait_group 0;" ::: "memory")

// ------------------------- prep: split X -------------------------
__global__ __launch_bounds__(256) void split_x_kernel(const float* __restrict__ x) {
    int n4 = 8192 * 512 / 4;
    for (int i = blockIdx.x * 256 + threadIdx.x; i < n4; i += gridDim.x * 256) {
        float4 v = ((const float4*)x)[i];
        u32 h0, l0, h1, l1;
        split2(v.x, v.y, h0, l0);
        split2(v.z, v.w, h1, l1);
        ((uint2*)g_xh)[i] = make_uint2(h0, h1);
        ((uint2*)g_xl)[i] = make_uint2(l0, l1);
    }
}

// ------------------------- prep: transpose + split W -------------------------
__global__ __launch_bounds__(256) void split_w_kernel(
    const float* __restrict__ Wq, const float* __restrict__ Wk, const float* __restrict__ Wv) {
    __shared__ float tile[64][65];
    int wh = blockIdx.x, w = wh >> 3, h = wh & 7, t = threadIdx.x;
    const float* W = (w == 0 ? Wq : (w == 1 ? Wk : Wv)) + h * 512 * 64;
    float c = (w == 0) ? 0.125f * 1.4426950408889634f : 1.0f;  // fold scale*log2(e) into Wq
    for (int k0 = 0; k0 < 512; k0 += 64) {
        __syncthreads();
        for (int e = t; e < 4096; e += 256)
            tile[e >> 6][e & 63] = W[(k0 + (e >> 6)) * 64 + (e & 63)] * c;
        __syncthreads();
        for (int e = t; e < 4096; e += 256) {
            int n = e >> 6, kk = e & 63;
            float f = tile[kk][n];
            __nv_bfloat16 hb = __float2bfloat16(f);
            int o = (wh * 64 + n) * 512 + k0 + kk;
            g_wth[o] = *(u16*)&hb;
            __nv_bfloat16 lb = __float2bfloat16(f - __bfloat162float(hb));
            g_wtl[o] = *(u16*)&lb;
        }
    }
}

// --------------------- QKV projection (HMMA + cp.async pipeline) ---------------------
// grid (64, 24). N=64, K=512 in 8 chunks of 64, double-buffered.
// smem bytes: Xh[b]=b*18432, Xl[b]=36864+b*18432, Wh[b]=73728+b*9216, Wl[b]=92160+b*9216
#define QK_SMEM 110592

__global__ __launch_bounds__(256, 2) void qkv_mma_kernel() {
    extern __shared__ u16 sm[];
    int t = threadIdx.x, w = t >> 5, lane = t & 31;
    int g = lane >> 2, tg = lane & 3;
    int m0 = blockIdx.x * 128, wh = blockIdx.y;

    u32 smS = sm_addr(sm);
    u32 aOff = (u32)((w * 16 + ((lane >> 3) & 1) * 8 + (lane & 7)) * 144 + (lane >> 4) * 16);
    u32 bOff = (u32)((lane & 7) * 144 + (lane >> 3) * 16);

    float acc[8][4];
    #pragma unroll
    for (int n = 0; n < 8; n++)
        #pragma unroll
        for (int e = 0; e < 4; e++) acc[n][e] = 0.0f;

    // issue chunk kb into buffer buf
    auto issue = [&](int kb, int buf) {
        int k0 = kb * 64;
        u32 xh = smS + buf * 18432, xl = smS + 36864 + buf * 18432;
        u32 wb = smS + 73728 + buf * 9216, wl = smS + 92160 + buf * 9216;
        #pragma unroll
        for (int it = 0; it < 4; it++) {
            int e = t + it * 256, r = e >> 3, u = e & 7;
            CP16(xh + r * 144 + u * 16, g_xh + (m0 + r) * 512 + k0 + u * 8);
            CP16(xl + r * 144 + u * 16, g_xl + (m0 + r) * 512 + k0 + u * 8);
        }
        #pragma unroll
        for (int it = 0; it < 2; it++) {
            int e = t + it * 256, r = e >> 3, u = e & 7;
            CP16(wb + r * 144 + u * 16, g_wth + (wh * 64 + r) * 512 + k0 + u * 8);
            CP16(wl + r * 144 + u * 16, g_wtl + (wh * 64 + r) * 512 + k0 + u * 8);
        }
        CPCOMMIT();
    };

    issue(0, 0);
    for (int kb = 0; kb < 8; kb++) {
        int buf = kb & 1;
        CPWAIT0();
        __syncthreads();
        if (kb < 7) issue(kb + 1, buf ^ 1);

        u32 XhB = smS + buf * 18432, XlB = smS + 36864 + buf * 18432;
        u32 WhB = smS + 73728 + buf * 9216, WlB = smS + 92160 + buf * 9216;
        #pragma unroll
        for (int kc2 = 0; kc2 < 2; kc2++) {
            u32 ah[2][4], al[2][4];
            ldmx4(ah[0], XhB + aOff + kc2 * 64);
            ldmx4(ah[1], XhB + aOff + kc2 * 64 + 32);
            ldmx4(al[0], XlB + aOff + kc2 * 64);
            ldmx4(al[1], XlB + aOff + kc2 * 64 + 32);
            #pragma unroll
            for (int ntg = 0; ntg < 2; ntg++) {
                u32 bf[4][4];
                #pragma unroll
                for (int j = 0; j < 4; j++)
                    ldmx4(bf[j], WhB + bOff + (ntg * 4 + j) * 8 * 144 + kc2 * 64);
                #pragma unroll
                for (int j = 0; j < 4; j++) mma16816(acc[ntg * 4 + j], ah[0], bf[j][0], bf[j][1]);
                #pragma unroll
                for (int j = 0; j < 4; j++) mma16816(acc[ntg * 4 + j], ah[1], bf[j][2], bf[j][3]);
                #pragma unroll
                for (int j = 0; j < 4; j++) mma16816(acc[ntg * 4 + j], al[0], bf[j][0], bf[j][1]);
                #pragma unroll
                for (int j = 0; j < 4; j++) mma16816(acc[ntg * 4 + j], al[1], bf[j][2], bf[j][3]);
                #pragma unroll
                for (int j = 0; j < 4; j++)
                    ldmx4(bf[j], WlB + bOff + (ntg * 4 + j) * 8 * 144 + kc2 * 64);
                #pragma unroll
                for (int j = 0; j < 4; j++) mma16816(acc[ntg * 4 + j], ah[0], bf[j][0], bf[j][1]);
                #pragma unroll
                for (int j = 0; j < 4; j++) mma16816(acc[ntg * 4 + j], ah[1], bf[j][2], bf[j][3]);
            }
        }
        __syncthreads();
    }

    // epilogue
    int m = m0 + w * 16 + g;
    int b = m >> 11, s = m & 2047;
    int wi = wh >> 3, h = wh & 7, bh = b * 8 + h;
    #pragma unroll
    for (int ntl = 0; ntl < 8; ntl++) {
        float c0 = acc[ntl][0], c1 = acc[ntl][1], c2 = acc[ntl][2], c3 = acc[ntl][3];
        if (wi < 2) {
            u32* oh = (u32*)(wi == 0 ? g_qh : g_kh);
            u32* ol = (u32*)(wi == 0 ? g_ql : g_kl);
            u32 hw, lw;
            split2(c0, c1, hw, lw);
            int i0 = (bh * 2048 + s) * 32 + ntl * 4 + tg;
            oh[i0] = hw; ol[i0] = lw;
            split2(c2, c3, hw, lw);
            int i1 = i0 + 8 * 32;
            oh[i1] = hw; ol[i1] = lw;
        } else {
            int d0 = ntl * 8 + 2 * tg;
            float cv[4] = {c0, c1, c2, c3};
            #pragma unroll
            for (int e = 0; e < 4; e++) {
                int d = d0 + (e & 1), ss = s + (e >> 1) * 8;
                __nv_bfloat16 hb = __float2bfloat16(cv[e]);
                __nv_bfloat16 lb = __float2bfloat16(cv[e] - __bfloat162float(hb));
                g_vth[(bh * 64 + d) * 2048 + ss] = *(u16*)&hb;
                g_vtl[(bh * 64 + d) * 2048 + ss] = *(u16*)&lb;
            }
        }
    }
}

// --------------------- attention (HMMA + cp.async pipeline) ---------------------
// grid (16, 32). 8 warps x 16 query rows. 32 KV tiles of 64, double-buffered.
// smem bytes: Qh 0, Ql 18432, Kh[b] 36864+b*9216, Kl[b] 55296+b*9216,
//             Vh[b] 73728+b*9216, Vl[b] 92160+b*9216
#define AT_SMEM 110592

__global__ __launch_bounds__(256, 2) void attn_mma_kernel(float* __restrict__ out) {
    extern __shared__ u16 sm[];
    u16* Qh = sm;            // [128][72]
    u16* Ql = sm + 9216;

    int t = threadIdx.x, w = t >> 5, lane = t & 31;
    int g = lane >> 2, tg = lane & 3;
    int q0 = blockIdx.x * 128, bh = blockIdx.y;

    u32 smS = sm_addr(sm);
    u32 QhS = smS, QlS = smS + 18432;
    u32 aOff = (u32)((w * 16 + ((lane >> 3) & 1) * 8 + (lane & 7)) * 144 + (lane >> 4) * 16);
    u32 kOff = (u32)((lane & 7) * 144 + (lane >> 3) * 16);
    u32 vOff = kOff;

    auto issue = [&](int kt, int buf) {
        int s0 = kt * 64;
        u32 kh = smS + 36864 + buf * 9216, kl = smS + 55296 + buf * 9216;
        u32 vh = smS + 73728 + buf * 9216, vl = smS + 92160 + buf * 9216;
        #pragma unroll
        for (int it = 0; it < 2; it++) {
            int e = t + it * 256, r = e >> 3, u = e & 7;
            CP16(kh + r * 144 + u * 16, g_kh + (bh * 2048 + s0 + r) * 64 + u * 8);
            CP16(kl + r * 144 + u * 16, g_kl + (bh * 2048 + s0 + r) * 64 + u * 8);
            CP16(vh + r * 144 + u * 16, g_vth + (bh * 64 + r) * 2048 + s0 + u * 8);
            CP16(vl + r * 144 + u * 16, g_vtl + (bh * 64 + r) * 2048 + s0 + u * 8);
        }
        CPCOMMIT();
    };

    // load Q tile (hi/lo)
    for (int e = t; e < 1024; e += 256) {
        int r = e >> 3, u = e & 7;
        int src = (bh * 2048 + q0 + r) * 64 + u * 8;
        *(uint4*)(Qh + r * 72 + u * 8) = *(const uint4*)(g_qh + src);
        *(uint4*)(Ql + r * 72 + u * 8) = *(const uint4*)(g_ql + src);
    }
    issue(0, 0);
    __syncthreads();

    // resident Q-hi fragments
    u32 qah[4][4];
    #pragma unroll
    for (int kc = 0; kc < 4; kc++) ldmx4(qah[kc], QhS + aOff + kc * 32);

    float oacc[8][4];
    #pragma unroll
    for (int n = 0; n < 8; n++)
        #pragma unroll
        for (int e = 0; e < 4; e++) oacc[n][e] = 0.0f;
    float l0 = 0.0f, l1 = 0.0f;

    for (int kt = 0; kt < 32; kt++) {
        int buf = kt & 1;
        CPWAIT0();
        __syncthreads();
        if (kt < 31) issue(kt + 1, buf ^ 1);

        u32 KhB = smS + 36864 + buf * 9216, KlB = smS + 55296 + buf * 9216;
        u32 VhB = smS + 73728 + buf * 9216, VlB = smS + 92160 + buf * 9216;

        // ---- S = Q K^T  (64 kv cols) ----
        float sacc[8][4];
        #pragma unroll
        for (int n = 0; n < 8; n++)
            #pragma unroll
            for (int e = 0; e < 4; e++) sacc[n][e] = 0.0f;

        #pragma unroll
        for (int kc2 = 0; kc2 < 2; kc2++) {
            u32 qal[2][4];
            ldmx4(qal[0], QlS + aOff + kc2 * 64);
            ldmx4(qal[1], QlS + aOff + kc2 * 64 + 32);
            #pragma unroll
            for (int ntg = 0; ntg < 2; ntg++) {
                u32 bf[4][4];
                #pragma unroll
                for (int j = 0; j < 4; j++)
                    ldmx4(bf[j], KhB + kOff + (ntg * 4 + j) * 8 * 144 + kc2 * 64);
                #pragma unroll
                for (int j = 0; j < 4; j++) mma16816(sacc[ntg * 4 + j], qah[2 * kc2],     bf[j][0], bf[j][1]);
                #pragma unroll
                for (int j = 0; j < 4; j++) mma16816(sacc[ntg * 4 + j], qah[2 * kc2 + 1], bf[j][2], bf[j][3]);
                #pragma unroll
                for (int j = 0; j < 4; j++) mma16816(sacc[ntg * 4 + j], qal[0], bf[j][0], bf[j][1]);
                #pragma unroll
                for (int j = 0; j < 4; j++) mma16816(sacc[ntg * 4 + j], qal[1], bf[j][2], bf[j][3]);
                #pragma unroll
                for (int j = 0; j < 4; j++)
                    ldmx4(bf[j], KlB + kOff + (ntg * 4 + j) * 8 * 144 + kc2 * 64);
                #pragma unroll
                for (int j = 0; j < 4; j++) mma16816(sacc[ntg * 4 + j], qah[2 * kc2],     bf[j][0], bf[j][1]);
                #pragma unroll
                for (int j = 0; j < 4; j++) mma16816(sacc[ntg * 4 + j], qah[2 * kc2 + 1], bf[j][2], bf[j][3]);
            }
        }

        // ---- softmax numerators: p = 2^s ----
        #pragma unroll
        for (int nt = 0; nt < 8; nt++) {
            sacc[nt][0] = ex2f(sacc[nt][0]);
            sacc[nt][1] = ex2f(sacc[nt][1]);
            sacc[nt][2] = ex2f(sacc[nt][2]);
            sacc[nt][3] = ex2f(sacc[nt][3]);
            l0 += sacc[nt][0] + sacc[nt][1];
            l1 += sacc[nt][2] + sacc[nt][3];
        }

        // ---- O += P V ----
        #pragma unroll
        for (int c2 = 0; c2 < 2; c2++) {
            u32 pah[2][4], pal[2][4];
            #pragma unroll
            for (int cc = 0; cc < 2; cc++) {
                int c = 2 * c2 + cc;
                split2(sacc[2 * c][0],     sacc[2 * c][1],     pah[cc][0], pal[cc][0]);
                split2(sacc[2 * c][2],     sacc[2 * c][3],     pah[cc][1], pal[cc][1]);
                split2(sacc[2 * c + 1][0], sacc[2 * c + 1][1], pah[cc][2], pal[cc][2]);
                split2(sacc[2 * c + 1][2], sacc[2 * c + 1][3], pah[cc][3], pal[cc][3]);
            }
            #pragma unroll
            for (int dtg = 0; dtg < 2; dtg++) {
                u32 vf[4][4];
                #pragma unroll
                for (int j = 0; j < 4; j++)
                    ldmx4(vf[j], VhB + vOff + (dtg * 4 + j) * 8 * 144 + c2 * 64);
                #pragma unroll
                for (int j = 0; j < 4; j++) mma16816(oacc[dtg * 4 + j], pah[0], vf[j][0], vf[j][1]);
                #pragma unroll
                for (int j = 0; j < 4; j++) mma16816(oacc[dtg * 4 + j], pah[1], vf[j][2], vf[j][3]);
                #pragma unroll
                for (int j = 0; j < 4; j++) mma16816(oacc[dtg * 4 + j], pal[0], vf[j][0], vf[j][1]);
                #pragma unroll
                for (int j = 0; j < 4; j++) mma16816(oacc[dtg * 4 + j], pal[1], vf[j][2], vf[j][3]);
                #pragma unroll
                for (int j = 0; j < 4; j++)
                    ldmx4(vf[j], VlB + vOff + (dtg * 4 + j) * 8 * 144 + c2 * 64);
                #pragma unroll
                for (int j = 0; j < 4; j++) mma16816(oacc[dtg * 4 + j], pah[0], vf[j][0], vf[j][1]);
                #pragma unroll
                for (int j = 0; j < 4; j++) mma16816(oacc[dtg * 4 + j], pah[1], vf[j][2], vf[j][3]);
            }
        }
        __syncthreads();
    }

    // row-sum reduce across the 4 threads of each row group
    l0 += __shfl_xor_sync(0xffffffffu, l0, 1);
    l0 += __shfl_xor_sync(0xffffffffu, l0, 2);
    l1 += __shfl_xor_sync(0xffffffffu, l1, 1);
    l1 += __shfl_xor_sync(0xffffffffu, l1, 2);
    float inv0 = 1.0f / l0, inv1 = 1.0f / l1;

    int b = bh >> 3, h = bh & 7;
    int s = q0 + w * 16 + g;
    float* o0 = out + ((b * 2048 + s) * 8 + h) * 64;
    float* o1 = out + ((b * 2048 + s + 8) * 8 + h) * 64;
    #pragma unroll
    for (int dt = 0; dt < 8; dt++) {
        *(float2*)(o0 + dt * 8 + 2 * tg) = make_float2(oacc[dt][0] * inv0, oacc[dt][1] * inv0);
        *(float2*)(o1 + dt * 8 + 2 * tg) = make_float2(oacc[dt][2] * inv1, oacc[dt][3] * inv1);
    }
}

extern "C" void kernel_launch(void* const* d_in, const int* in_sizes, int n_in,
                              void* d_out, int out_size)
{
    const float* x  = (const float*)d_in[0];
    const float* Wq = (const float*)d_in[1];
    const float* Wk = (const float*)d_in[2];
    const float* Wv = (const float*)d_in[3];
    float* out = (float*)d_out;

    cudaFuncSetAttribute(qkv_mma_kernel,  cudaFuncAttributeMaxDynamicSharedMemorySize, QK_SMEM);
    cudaFuncSetAttribute(attn_mma_kernel, cudaFuncAttributeMaxDynamicSharedMemorySize, AT_SMEM);

    split_x_kernel<<<512, 256>>>(x);
    split_w_kernel<<<24, 256>>>(Wq, Wk, Wv);
    qkv_mma_kernel<<<dim3(64, 24), 256, QK_SMEM>>>();
    attn_mma_kernel<<<dim3(16, 32), 256, AT_SMEM>>>(out);
}

// round 12
// speedup vs baseline: 6.3120x; 1.2858x over previous
#include <cuda_runtime.h>
#include <cuda_bf16.h>
#include <cuda_fp16.h>

typedef unsigned int u32;
typedef unsigned short u16;

// ------------------------- scratch -------------------------
__device__ u16 g_xh[8192 * 512];
__device__ u16 g_xl[8192 * 512];
__device__ u16 g_wth[24 * 64 * 512];   // [wh][n=dh][k=d] transposed (bf16)
__device__ u16 g_wtl[24 * 64 * 512];
__device__ u16 g_qh[32 * 2048 * 64];   // [bh][s][dh] fp16 hi
__device__ u16 g_ql[32 * 2048 * 64];   // fp16 residual
__device__ u16 g_kh[32 * 2048 * 64];   // fp16 single
__device__ u16 g_vth[32 * 64 * 2048];  // [bh][dh][s] transposed, fp16 single

// ------------------------- helpers -------------------------
__device__ __forceinline__ float ex2f(float x) {
    float y;
    asm("ex2.approx.f32 %0, %1;" : "=f"(y) : "f"(x));
    return y;
}
// bf16 split (QKV inputs)
__device__ __forceinline__ void split2(float f0, float f1, u32& hi, u32& lo) {
    asm("cvt.rn.bf16x2.f32 %0, %1, %2;" : "=r"(hi) : "f"(f1), "f"(f0));
    float h0 = __uint_as_float(hi << 16);
    float h1 = __uint_as_float(hi & 0xffff0000u);
    asm("cvt.rn.bf16x2.f32 %0, %1, %2;" : "=r"(lo) : "f"(f1 - h1), "f"(f0 - h0));
}
// fp16 split (Q, P)
__device__ __forceinline__ void split2h(float f0, float f1, u32& hi, u32& lo) {
    asm("cvt.rn.f16x2.f32 %0, %1, %2;" : "=r"(hi) : "f"(f1), "f"(f0));
    float h0, h1;
    asm("{\n\t.reg .f16 a, b;\n\tmov.b32 {a, b}, %2;\n\t"
        "cvt.f32.f16 %0, a;\n\tcvt.f32.f16 %1, b;\n\t}"
        : "=f"(h0), "=f"(h1) : "r"(hi));
    asm("cvt.rn.f16x2.f32 %0, %1, %2;" : "=r"(lo) : "f"(f1 - h1), "f"(f0 - h0));
}
__device__ __forceinline__ u32 pack2h(float f0, float f1) {
    u32 r;
    asm("cvt.rn.f16x2.f32 %0, %1, %2;" : "=r"(r) : "f"(f1), "f"(f0));
    return r;
}
// bf16 mma (QKV)
__device__ __forceinline__ void mma16816(float* c, const u32* a, u32 b0, u32 b1) {
    asm volatile(
        "mma.sync.aligned.m16n8k16.row.col.f32.bf16.bf16.f32 "
        "{%0,%1,%2,%3}, {%4,%5,%6,%7}, {%8,%9}, {%0,%1,%2,%3};"
        : "+f"(c[0]), "+f"(c[1]), "+f"(c[2]), "+f"(c[3])
        : "r"(a[0]), "r"(a[1]), "r"(a[2]), "r"(a[3]), "r"(b0), "r"(b1));
}
// fp16 mma (attention)
__device__ __forceinline__ void mma16816h(float* c, const u32* a, u32 b0, u32 b1) {
    asm volatile(
        "mma.sync.aligned.m16n8k16.row.col.f32.f16.f16.f32 "
        "{%0,%1,%2,%3}, {%4,%5,%6,%7}, {%8,%9}, {%0,%1,%2,%3};"
        : "+f"(c[0]), "+f"(c[1]), "+f"(c[2]), "+f"(c[3])
        : "r"(a[0]), "r"(a[1]), "r"(a[2]), "r"(a[3]), "r"(b0), "r"(b1));
}
__device__ __forceinline__ void ldmx4(u32* r, u32 saddr) {
    asm volatile("ldmatrix.sync.aligned.m8n8.x4.shared.b16 {%0,%1,%2,%3}, [%4];"
        : "=r"(r[0]), "=r"(r[1]), "=r"(r[2]), "=r"(r[3]) : "r"(saddr));
}
__device__ __forceinline__ u32 sm_addr(const void* p) {
    return (u32)__cvta_generic_to_shared(p);
}
#define CP16(smB, gp)  asm volatile("cp.async.cg.shared.global [%0], [%1], 16;" :: "r"(smB), "l"(gp) : "memory")
#define CPCOMMIT()     asm volatile("cp.async.commit_group;" ::: "memory")
#define CPWAIT0()      asm volatile("cp.async.wait_group 0;" ::: "memory")

// ------------------------- prep: split X -------------------------
__global__ __launch_bounds__(256) void split_x_kernel(const float* __restrict__ x) {
    int n4 = 8192 * 512 / 4;
    for (int i = blockIdx.x * 256 + threadIdx.x; i < n4; i += gridDim.x * 256) {
        float4 v = ((const float4*)x)[i];
        u32 h0, l0, h1, l1;
        split2(v.x, v.y, h0, l0);
        split2(v.z, v.w, h1, l1);
        ((uint2*)g_xh)[i] = make_uint2(h0, h1);
        ((uint2*)g_xl)[i] = make_uint2(l0, l1);
    }
}

// ------------------------- prep: transpose + split W -------------------------
__global__ __launch_bounds__(256) void split_w_kernel(
    const float* __restrict__ Wq, const float* __restrict__ Wk, const float* __restrict__ Wv) {
    __shared__ float tile[64][65];
    int wh = blockIdx.x, w = wh >> 3, h = wh & 7, t = threadIdx.x;
    const float* W = (w == 0 ? Wq : (w == 1 ? Wk : Wv)) + h * 512 * 64;
    float c = (w == 0) ? 0.125f * 1.4426950408889634f : 1.0f;  // fold scale*log2(e) into Wq
    for (int k0 = 0; k0 < 512; k0 += 64) {
        __syncthreads();
        for (int e = t; e < 4096; e += 256)
            tile[e >> 6][e & 63] = W[(k0 + (e >> 6)) * 64 + (e & 63)] * c;
        __syncthreads();
        for (int e = t; e < 4096; e += 256) {
            int n = e >> 6, kk = e & 63;
            float f = tile[kk][n];
            __nv_bfloat16 hb = __float2bfloat16(f);
            int o = (wh * 64 + n) * 512 + k0 + kk;
            g_wth[o] = *(u16*)&hb;
            __nv_bfloat16 lb = __float2bfloat16(f - __bfloat162float(hb));
            g_wtl[o] = *(u16*)&lb;
        }
    }
}

// --------------------- QKV projection (bf16 HMMA + cp.async pipeline) ---------------------
// grid (64, 24). N=64, K=512 in 8 chunks of 64, double-buffered.
#define QK_SMEM 110592

__global__ __launch_bounds__(256, 2) void qkv_mma_kernel() {
    extern __shared__ u16 sm[];
    int t = threadIdx.x, w = t >> 5, lane = t & 31;
    int g = lane >> 2, tg = lane & 3;
    int m0 = blockIdx.x * 128, wh = blockIdx.y;

    u32 smS = sm_addr(sm);
    u32 aOff = (u32)((w * 16 + ((lane >> 3) & 1) * 8 + (lane & 7)) * 144 + (lane >> 4) * 16);
    u32 bOff = (u32)((lane & 7) * 144 + (lane >> 3) * 16);

    float acc[8][4];
    #pragma unroll
    for (int n = 0; n < 8; n++)
        #pragma unroll
        for (int e = 0; e < 4; e++) acc[n][e] = 0.0f;

    auto issue = [&](int kb, int buf) {
        int k0 = kb * 64;
        u32 xh = smS + buf * 18432, xl = smS + 36864 + buf * 18432;
        u32 wb = smS + 73728 + buf * 9216, wl = smS + 92160 + buf * 9216;
        #pragma unroll
        for (int it = 0; it < 4; it++) {
            int e = t + it * 256, r = e >> 3, u = e & 7;
            CP16(xh + r * 144 + u * 16, g_xh + (m0 + r) * 512 + k0 + u * 8);
            CP16(xl + r * 144 + u * 16, g_xl + (m0 + r) * 512 + k0 + u * 8);
        }
        #pragma unroll
        for (int it = 0; it < 2; it++) {
            int e = t + it * 256, r = e >> 3, u = e & 7;
            CP16(wb + r * 144 + u * 16, g_wth + (wh * 64 + r) * 512 + k0 + u * 8);
            CP16(wl + r * 144 + u * 16, g_wtl + (wh * 64 + r) * 512 + k0 + u * 8);
        }
        CPCOMMIT();
    };

    issue(0, 0);
    for (int kb = 0; kb < 8; kb++) {
        int buf = kb & 1;
        CPWAIT0();
        __syncthreads();
        if (kb < 7) issue(kb + 1, buf ^ 1);

        u32 XhB = smS + buf * 18432, XlB = smS + 36864 + buf * 18432;
        u32 WhB = smS + 73728 + buf * 9216, WlB = smS + 92160 + buf * 9216;
        #pragma unroll
        for (int kc2 = 0; kc2 < 2; kc2++) {
            u32 ah[2][4], al[2][4];
            ldmx4(ah[0], XhB + aOff + kc2 * 64);
            ldmx4(ah[1], XhB + aOff + kc2 * 64 + 32);
            ldmx4(al[0], XlB + aOff + kc2 * 64);
            ldmx4(al[1], XlB + aOff + kc2 * 64 + 32);
            #pragma unroll
            for (int ntg = 0; ntg < 2; ntg++) {
                u32 bf[4][4];
                #pragma unroll
                for (int j = 0; j < 4; j++)
                    ldmx4(bf[j], WhB + bOff + (ntg * 4 + j) * 8 * 144 + kc2 * 64);
                #pragma unroll
                for (int j = 0; j < 4; j++) mma16816(acc[ntg * 4 + j], ah[0], bf[j][0], bf[j][1]);
                #pragma unroll
                for (int j = 0; j < 4; j++) mma16816(acc[ntg * 4 + j], ah[1], bf[j][2], bf[j][3]);
                #pragma unroll
                for (int j = 0; j < 4; j++) mma16816(acc[ntg * 4 + j], al[0], bf[j][0], bf[j][1]);
                #pragma unroll
                for (int j = 0; j < 4; j++) mma16816(acc[ntg * 4 + j], al[1], bf[j][2], bf[j][3]);
                #pragma unroll
                for (int j = 0; j < 4; j++)
                    ldmx4(bf[j], WlB + bOff + (ntg * 4 + j) * 8 * 144 + kc2 * 64);
                #pragma unroll
                for (int j = 0; j < 4; j++) mma16816(acc[ntg * 4 + j], ah[0], bf[j][0], bf[j][1]);
                #pragma unroll
                for (int j = 0; j < 4; j++) mma16816(acc[ntg * 4 + j], ah[1], bf[j][2], bf[j][3]);
            }
        }
        __syncthreads();
    }

    // epilogue: Q -> fp16 split, K -> fp16 single, V -> fp16 single transposed
    int m = m0 + w * 16 + g;
    int b = m >> 11, s = m & 2047;
    int wi = wh >> 3, h = wh & 7, bh = b * 8 + h;
    #pragma unroll
    for (int ntl = 0; ntl < 8; ntl++) {
        float c0 = acc[ntl][0], c1 = acc[ntl][1], c2 = acc[ntl][2], c3 = acc[ntl][3];
        if (wi == 0) {
            u32 hw, lw;
            split2h(c0, c1, hw, lw);
            int i0 = (bh * 2048 + s) * 32 + ntl * 4 + tg;
            ((u32*)g_qh)[i0] = hw; ((u32*)g_ql)[i0] = lw;
            split2h(c2, c3, hw, lw);
            int i1 = i0 + 8 * 32;
            ((u32*)g_qh)[i1] = hw; ((u32*)g_ql)[i1] = lw;
        } else if (wi == 1) {
            int i0 = (bh * 2048 + s) * 32 + ntl * 4 + tg;
            ((u32*)g_kh)[i0] = pack2h(c0, c1);
            ((u32*)g_kh)[i0 + 8 * 32] = pack2h(c2, c3);
        } else {
            int d0 = ntl * 8 + 2 * tg;
            float cv[4] = {c0, c1, c2, c3};
            #pragma unroll
            for (int e = 0; e < 4; e++) {
                int d = d0 + (e & 1), ss = s + (e >> 1) * 8;
                __half hv = __float2half(cv[e]);
                g_vth[(bh * 64 + d) * 2048 + ss] = *(u16*)&hv;
            }
        }
    }
}

// --------------------- attention (fp16 HMMA + cp.async pipeline) ---------------------
// grid (16, 32). 8 warps x 16 query rows. 32 KV tiles of 64, double-buffered.
// smem bytes: Qh 0, Ql 18432, Kh[b] 36864+b*9216, Vh[b] 55296+b*9216
#define AT_SMEM 73728

__global__ __launch_bounds__(256, 2) void attn_mma_kernel(float* __restrict__ out) {
    extern __shared__ u16 sm[];
    u16* Qh = sm;            // [128][72] fp16 hi
    u16* Ql = sm + 9216;     // (offset in u16 units: 18432B/2)

    int t = threadIdx.x, w = t >> 5, lane = t & 31;
    int g = lane >> 2, tg = lane & 3;
    int q0 = blockIdx.x * 128, bh = blockIdx.y;

    u32 smS = sm_addr(sm);
    u32 QhS = smS, QlS = smS + 18432;
    u32 aOff = (u32)((w * 16 + ((lane >> 3) & 1) * 8 + (lane & 7)) * 144 + (lane >> 4) * 16);
    u32 kOff = (u32)((lane & 7) * 144 + (lane >> 3) * 16);

    auto issue = [&](int kt, int buf) {
        int s0 = kt * 64;
        u32 kh = smS + 36864 + buf * 9216;
        u32 vh = smS + 55296 + buf * 9216;
        #pragma unroll
        for (int it = 0; it < 2; it++) {
            int e = t + it * 256, r = e >> 3, u = e & 7;
            CP16(kh + r * 144 + u * 16, g_kh + (bh * 2048 + s0 + r) * 64 + u * 8);
            CP16(vh + r * 144 + u * 16, g_vth + (bh * 64 + r) * 2048 + s0 + u * 8);
        }
        CPCOMMIT();
    };

    // load Q tile (hi/lo)
    for (int e = t; e < 1024; e += 256) {
        int r = e >> 3, u = e & 7;
        int src = (bh * 2048 + q0 + r) * 64 + u * 8;
        *(uint4*)(Qh + r * 72 + u * 8) = *(const uint4*)(g_qh + src);
        *(uint4*)(Ql + r * 72 + u * 8) = *(const uint4*)(g_ql + src);
    }
    issue(0, 0);
    __syncthreads();

    // resident Q-hi fragments
    u32 qah[4][4];
    #pragma unroll
    for (int kc = 0; kc < 4; kc++) ldmx4(qah[kc], QhS + aOff + kc * 32);

    float oacc[8][4];
    #pragma unroll
    for (int n = 0; n < 8; n++)
        #pragma unroll
        for (int e = 0; e < 4; e++) oacc[n][e] = 0.0f;
    float l0 = 0.0f, l1 = 0.0f;

    for (int kt = 0; kt < 32; kt++) {
        int buf = kt & 1;
        CPWAIT0();
        __syncthreads();
        if (kt < 31) issue(kt + 1, buf ^ 1);

        u32 KhB = smS + 36864 + buf * 9216;
        u32 VhB = smS + 55296 + buf * 9216;

        // ---- S = Q K^T  (64 kv cols), 2-term fp16: QhK + QlK ----
        float sacc[8][4];
        #pragma unroll
        for (int n = 0; n < 8; n++)
            #pragma unroll
            for (int e = 0; e < 4; e++) sacc[n][e] = 0.0f;

        #pragma unroll
        for (int kc2 = 0; kc2 < 2; kc2++) {
            u32 qal[2][4];
            ldmx4(qal[0], QlS + aOff + kc2 * 64);
            ldmx4(qal[1], QlS + aOff + kc2 * 64 + 32);
            #pragma unroll
            for (int ntg = 0; ntg < 2; ntg++) {
                u32 bf[4][4];
                #pragma unroll
                for (int j = 0; j < 4; j++)
                    ldmx4(bf[j], KhB + kOff + (ntg * 4 + j) * 8 * 144 + kc2 * 64);
                #pragma unroll
                for (int j = 0; j < 4; j++) mma16816h(sacc[ntg * 4 + j], qah[2 * kc2],     bf[j][0], bf[j][1]);
                #pragma unroll
                for (int j = 0; j < 4; j++) mma16816h(sacc[ntg * 4 + j], qah[2 * kc2 + 1], bf[j][2], bf[j][3]);
                #pragma unroll
                for (int j = 0; j < 4; j++) mma16816h(sacc[ntg * 4 + j], qal[0], bf[j][0], bf[j][1]);
                #pragma unroll
                for (int j = 0; j < 4; j++) mma16816h(sacc[ntg * 4 + j], qal[1], bf[j][2], bf[j][3]);
            }
        }

        // ---- softmax numerators: p = 2^s ----
        #pragma unroll
        for (int nt = 0; nt < 8; nt++) {
            sacc[nt][0] = ex2f(sacc[nt][0]);
            sacc[nt][1] = ex2f(sacc[nt][1]);
            sacc[nt][2] = ex2f(sacc[nt][2]);
            sacc[nt][3] = ex2f(sacc[nt][3]);
            l0 += sacc[nt][0] + sacc[nt][1];
            l1 += sacc[nt][2] + sacc[nt][3];
        }

        // ---- O += P V  (2-term fp16: PhV + PlV) ----
        #pragma unroll
        for (int c2 = 0; c2 < 2; c2++) {
            u32 pah[2][4], pal[2][4];
            #pragma unroll
            for (int cc = 0; cc < 2; cc++) {
                int c = 2 * c2 + cc;
                split2h(sacc[2 * c][0],     sacc[2 * c][1],     pah[cc][0], pal[cc][0]);
                split2h(sacc[2 * c][2],     sacc[2 * c][3],     pah[cc][1], pal[cc][1]);
                split2h(sacc[2 * c + 1][0], sacc[2 * c + 1][1], pah[cc][2], pal[cc][2]);
                split2h(sacc[2 * c + 1][2], sacc[2 * c + 1][3], pah[cc][3], pal[cc][3]);
            }
            #pragma unroll
            for (int dtg = 0; dtg < 2; dtg++) {
                u32 vf[4][4];
                #pragma unroll
                for (int j = 0; j < 4; j++)
                    ldmx4(vf[j], VhB + kOff + (dtg * 4 + j) * 8 * 144 + c2 * 64);
                #pragma unroll
                for (int j = 0; j < 4; j++) mma16816h(oacc[dtg * 4 + j], pah[0], vf[j][0], vf[j][1]);
                #pragma unroll
                for (int j = 0; j < 4; j++) mma16816h(oacc[dtg * 4 + j], pah[1], vf[j][2], vf[j][3]);
                #pragma unroll
                for (int j = 0; j < 4; j++) mma16816h(oacc[dtg * 4 + j], pal[0], vf[j][0], vf[j][1]);
                #pragma unroll
                for (int j = 0; j < 4; j++) mma16816h(oacc[dtg * 4 + j], pal[1], vf[j][2], vf[j][3]);
            }
        }
        __syncthreads();
    }

    // row-sum reduce across the 4 threads of each row group
    l0 += __shfl_xor_sync(0xffffffffu, l0, 1);
    l0 += __shfl_xor_sync(0xffffffffu, l0, 2);
    l1 += __shfl_xor_sync(0xffffffffu, l1, 1);
    l1 += __shfl_xor_sync(0xffffffffu, l1, 2);
    float inv0 = 1.0f / l0, inv1 = 1.0f / l1;

    int b = bh >> 3, h = bh & 7;
    int s = q0 + w * 16 + g;
    float* o0 = out + ((b * 2048 + s) * 8 + h) * 64;
    float* o1 = out + ((b * 2048 + s + 8) * 8 + h) * 64;
    #pragma unroll
    for (int dt = 0; dt < 8; dt++) {
        *(float2*)(o0 + dt * 8 + 2 * tg) = make_float2(oacc[dt][0] * inv0, oacc[dt][1] * inv0);
        *(float2*)(o1 + dt * 8 + 2 * tg) = make_float2(oacc[dt][2] * inv1, oacc[dt][3] * inv1);
    }
}

extern "C" void kernel_launch(void* const* d_in, const int* in_sizes, int n_in,
                              void* d_out, int out_size)
{
    const float* x  = (const float*)d_in[0];
    const float* Wq = (const float*)d_in[1];
    const float* Wk = (const float*)d_in[2];
    const float* Wv = (const float*)d_in[3];
    float* out = (float*)d_out;

    cudaFuncSetAttribute(qkv_mma_kernel,  cudaFuncAttributeMaxDynamicSharedMemorySize, QK_SMEM);
    cudaFuncSetAttribute(attn_mma_kernel, cudaFuncAttributeMaxDynamicSharedMemorySize, AT_SMEM);

    split_x_kernel<<<512, 256>>>(x);
    split_w_kernel<<<24, 256>>>(Wq, Wk, Wv);
    qkv_mma_kernel<<<dim3(64, 24), 256, QK_SMEM>>>();
    attn_mma_kernel<<<dim3(16, 32), 256, AT_SMEM>>>(out);
}

// round 17
// speedup vs baseline: 7.8544x; 1.2444x over previous
#include <cuda_runtime.h>
#include <cuda_bf16.h>
#include <cuda_fp16.h>

typedef unsigned int u32;
typedef unsigned short u16;

// ------------------------- scratch -------------------------
__device__ u16 g_xh[8192 * 512];       // fp16 hi of x
__device__ u16 g_xl[8192 * 512];       // fp16 residual of x
__device__ u16 g_wth[24 * 64 * 512];   // [wh][n=dh][k=d] transposed, fp16 single
__device__ u16 g_qh[32 * 2048 * 64];   // [bh][s][dh] fp16 hi
__device__ u16 g_ql[32 * 2048 * 64];   // fp16 residual
__device__ u16 g_kh[32 * 2048 * 64];   // fp16 single
__device__ u16 g_vth[32 * 64 * 2048];  // [bh][dh][s] transposed, fp16 single

// ------------------------- helpers -------------------------
__device__ __forceinline__ float ex2f(float x) {
    float y;
    asm("ex2.approx.f32 %0, %1;" : "=f"(y) : "f"(x));
    return y;
}
// fp16 split: hi = f16x2{lower=f0, upper=f1}, lo = residuals
__device__ __forceinline__ void split2h(float f0, float f1, u32& hi, u32& lo) {
    asm("cvt.rn.f16x2.f32 %0, %1, %2;" : "=r"(hi) : "f"(f1), "f"(f0));
    float h0, h1;
    asm("{\n\t.reg .f16 a, b;\n\tmov.b32 {a, b}, %2;\n\t"
        "cvt.f32.f16 %0, a;\n\tcvt.f32.f16 %1, b;\n\t}"
        : "=f"(h0), "=f"(h1) : "r"(hi));
    asm("cvt.rn.f16x2.f32 %0, %1, %2;" : "=r"(lo) : "f"(f1 - h1), "f"(f0 - h0));
}
__device__ __forceinline__ u32 pack2h(float f0, float f1) {
    u32 r;
    asm("cvt.rn.f16x2.f32 %0, %1, %2;" : "=r"(r) : "f"(f1), "f"(f0));
    return r;
}
// fp16 mma
__device__ __forceinline__ void mma16816h(float* c, const u32* a, u32 b0, u32 b1) {
    asm volatile(
        "mma.sync.aligned.m16n8k16.row.col.f32.f16.f16.f32 "
        "{%0,%1,%2,%3}, {%4,%5,%6,%7}, {%8,%9}, {%0,%1,%2,%3};"
        : "+f"(c[0]), "+f"(c[1]), "+f"(c[2]), "+f"(c[3])
        : "r"(a[0]), "r"(a[1]), "r"(a[2]), "r"(a[3]), "r"(b0), "r"(b1));
}
__device__ __forceinline__ void ldmx4(u32* r, u32 saddr) {
    asm volatile("ldmatrix.sync.aligned.m8n8.x4.shared.b16 {%0,%1,%2,%3}, [%4];"
        : "=r"(r[0]), "=r"(r[1]), "=r"(r[2]), "=r"(r[3]) : "r"(saddr));
}
__device__ __forceinline__ u32 sm_addr(const void* p) {
    return (u32)__cvta_generic_to_shared(p);
}
#define CP16(smB, gp)  asm volatile("cp.async.cg.shared.global [%0], [%1], 16;" :: "r"(smB), "l"(gp) : "memory")
#define CPCOMMIT()     asm volatile("cp.async.commit_group;" ::: "memory")
#define CPWAIT0()      asm volatile("cp.async.wait_group 0;" ::: "memory")

// ------------------------- prep: split X (fp16 hi/lo) -------------------------
__global__ __launch_bounds__(256) void split_x_kernel(const float* __restrict__ x) {
    int n4 = 8192 * 512 / 4;
    for (int i = blockIdx.x * 256 + threadIdx.x; i < n4; i += gridDim.x * 256) {
        float4 v = ((const float4*)x)[i];
        u32 h0, l0, h1, l1;
        split2h(v.x, v.y, h0, l0);
        split2h(v.z, v.w, h1, l1);
        ((uint2*)g_xh)[i] = make_uint2(h0, h1);
        ((uint2*)g_xl)[i] = make_uint2(l0, l1);
    }
}

// ------------------------- prep: transpose W (fp16 single) -------------------------
__global__ __launch_bounds__(256) void split_w_kernel(
    const float* __restrict__ Wq, const float* __restrict__ Wk, const float* __restrict__ Wv) {
    __shared__ float tile[64][65];
    int wh = blockIdx.x, w = wh >> 3, h = wh & 7, t = threadIdx.x;
    const float* W = (w == 0 ? Wq : (w == 1 ? Wk : Wv)) + h * 512 * 64;
    float c = (w == 0) ? 0.125f * 1.4426950408889634f : 1.0f;  // fold scale*log2(e) into Wq
    for (int k0 = 0; k0 < 512; k0 += 64) {
        __syncthreads();
        for (int e = t; e < 4096; e += 256)
            tile[e >> 6][e & 63] = W[(k0 + (e >> 6)) * 64 + (e & 63)] * c;
        __syncthreads();
        for (int e = t; e < 4096; e += 256) {
            int n = e >> 6, kk = e & 63;
            __half hv = __float2half(tile[kk][n]);
            g_wth[(wh * 64 + n) * 512 + k0 + kk] = *(u16*)&hv;
        }
    }
}

// --------------------- QKV projection (fp16 2-term + cp.async pipeline) ---------------------
// grid (64, 24). N=64, K=512 in 8 chunks of 64, double-buffered.
// smem: Xh[b]=b*18432, Xl[b]=36864+b*18432, Wh[b]=73728+b*9216
#define QK_SMEM 92160

__global__ __launch_bounds__(256, 2) void qkv_mma_kernel() {
    extern __shared__ u16 sm[];
    int t = threadIdx.x, w = t >> 5, lane = t & 31;
    int g = lane >> 2, tg = lane & 3;
    int m0 = blockIdx.x * 128, wh = blockIdx.y;

    u32 smS = sm_addr(sm);
    u32 aOff = (u32)((w * 16 + ((lane >> 3) & 1) * 8 + (lane & 7)) * 144 + (lane >> 4) * 16);
    u32 bOff = (u32)((lane & 7) * 144 + (lane >> 3) * 16);

    float acc[8][4];
    #pragma unroll
    for (int n = 0; n < 8; n++)
        #pragma unroll
        for (int e = 0; e < 4; e++) acc[n][e] = 0.0f;

    auto issue = [&](int kb, int buf) {
        int k0 = kb * 64;
        u32 xh = smS + buf * 18432, xl = smS + 36864 + buf * 18432;
        u32 wb = smS + 73728 + buf * 9216;
        #pragma unroll
        for (int it = 0; it < 4; it++) {
            int e = t + it * 256, r = e >> 3, u = e & 7;
            CP16(xh + r * 144 + u * 16, g_xh + (m0 + r) * 512 + k0 + u * 8);
            CP16(xl + r * 144 + u * 16, g_xl + (m0 + r) * 512 + k0 + u * 8);
        }
        #pragma unroll
        for (int it = 0; it < 2; it++) {
            int e = t + it * 256, r = e >> 3, u = e & 7;
            CP16(wb + r * 144 + u * 16, g_wth + (wh * 64 + r) * 512 + k0 + u * 8);
        }
        CPCOMMIT();
    };

    issue(0, 0);
    for (int kb = 0; kb < 8; kb++) {
        int buf = kb & 1;
        CPWAIT0();
        __syncthreads();
        if (kb < 7) issue(kb + 1, buf ^ 1);

        u32 XhB = smS + buf * 18432, XlB = smS + 36864 + buf * 18432;
        u32 WhB = smS + 73728 + buf * 9216;
        #pragma unroll
        for (int kc2 = 0; kc2 < 2; kc2++) {
            u32 ah[2][4], al[2][4];
            ldmx4(ah[0], XhB + aOff + kc2 * 64);
            ldmx4(ah[1], XhB + aOff + kc2 * 64 + 32);
            ldmx4(al[0], XlB + aOff + kc2 * 64);
            ldmx4(al[1], XlB + aOff + kc2 * 64 + 32);
            #pragma unroll
            for (int ntg = 0; ntg < 2; ntg++) {
                u32 bf[4][4];
                #pragma unroll
                for (int j = 0; j < 4; j++)
                    ldmx4(bf[j], WhB + bOff + (ntg * 4 + j) * 8 * 144 + kc2 * 64);
                #pragma unroll
                for (int j = 0; j < 4; j++) mma16816h(acc[ntg * 4 + j], ah[0], bf[j][0], bf[j][1]);
                #pragma unroll
                for (int j = 0; j < 4; j++) mma16816h(acc[ntg * 4 + j], ah[1], bf[j][2], bf[j][3]);
                #pragma unroll
                for (int j = 0; j < 4; j++) mma16816h(acc[ntg * 4 + j], al[0], bf[j][0], bf[j][1]);
                #pragma unroll
                for (int j = 0; j < 4; j++) mma16816h(acc[ntg * 4 + j], al[1], bf[j][2], bf[j][3]);
            }
        }
        __syncthreads();
    }

    // epilogue: Q -> fp16 split, K -> fp16 single, V -> fp16 single transposed
    int m = m0 + w * 16 + g;
    int b = m >> 11, s = m & 2047;
    int wi = wh >> 3, h = wh & 7, bh = b * 8 + h;
    #pragma unroll
    for (int ntl = 0; ntl < 8; ntl++) {
        float c0 = acc[ntl][0], c1 = acc[ntl][1], c2 = acc[ntl][2], c3 = acc[ntl][3];
        if (wi == 0) {
            u32 hw, lw;
            split2h(c0, c1, hw, lw);
            int i0 = (bh * 2048 + s) * 32 + ntl * 4 + tg;
            ((u32*)g_qh)[i0] = hw; ((u32*)g_ql)[i0] = lw;
            split2h(c2, c3, hw, lw);
            int i1 = i0 + 8 * 32;
            ((u32*)g_qh)[i1] = hw; ((u32*)g_ql)[i1] = lw;
        } else if (wi == 1) {
            int i0 = (bh * 2048 + s) * 32 + ntl * 4 + tg;
            ((u32*)g_kh)[i0] = pack2h(c0, c1);
            ((u32*)g_kh)[i0 + 8 * 32] = pack2h(c2, c3);
        } else {
            int d0 = ntl * 8 + 2 * tg;
            float cv[4] = {c0, c1, c2, c3};
            #pragma unroll
            for (int e = 0; e < 4; e++) {
                int d = d0 + (e & 1), ss = s + (e >> 1) * 8;
                __half hv = __float2half(cv[e]);
                g_vth[(bh * 64 + d) * 2048 + ss] = *(u16*)&hv;
            }
        }
    }
}

// --------------------- attention (fp16: S 2-term, PV 1-term) ---------------------
// grid (16, 32). 8 warps x 16 query rows. 32 KV tiles of 64, double-buffered.
// smem: Qh 0, Ql 18432, Kh[b] 36864+b*9216, Vh[b] 55296+b*9216
#define AT_SMEM 73728

__global__ __launch_bounds__(256, 2) void attn_mma_kernel(float* __restrict__ out) {
    extern __shared__ u16 sm[];
    u16* Qh = sm;            // [128][72] fp16 hi
    u16* Ql = sm + 9216;

    int t = threadIdx.x, w = t >> 5, lane = t & 31;
    int g = lane >> 2, tg = lane & 3;
    int q0 = blockIdx.x * 128, bh = blockIdx.y;

    u32 smS = sm_addr(sm);
    u32 QhS = smS, QlS = smS + 18432;
    u32 aOff = (u32)((w * 16 + ((lane >> 3) & 1) * 8 + (lane & 7)) * 144 + (lane >> 4) * 16);
    u32 kOff = (u32)((lane & 7) * 144 + (lane >> 3) * 16);

    auto issue = [&](int kt, int buf) {
        int s0 = kt * 64;
        u32 kh = smS + 36864 + buf * 9216;
        u32 vh = smS + 55296 + buf * 9216;
        #pragma unroll
        for (int it = 0; it < 2; it++) {
            int e = t + it * 256, r = e >> 3, u = e & 7;
            CP16(kh + r * 144 + u * 16, g_kh + (bh * 2048 + s0 + r) * 64 + u * 8);
            CP16(vh + r * 144 + u * 16, g_vth + (bh * 64 + r) * 2048 + s0 + u * 8);
        }
        CPCOMMIT();
    };

    // load Q tile (hi/lo)
    for (int e = t; e < 1024; e += 256) {
        int r = e >> 3, u = e & 7;
        int src = (bh * 2048 + q0 + r) * 64 + u * 8;
        *(uint4*)(Qh + r * 72 + u * 8) = *(const uint4*)(g_qh + src);
        *(uint4*)(Ql + r * 72 + u * 8) = *(const uint4*)(g_ql + src);
    }
    issue(0, 0);
    __syncthreads();

    // resident Q-hi fragments
    u32 qah[4][4];
    #pragma unroll
    for (int kc = 0; kc < 4; kc++) ldmx4(qah[kc], QhS + aOff + kc * 32);

    float oacc[8][4];
    #pragma unroll
    for (int n = 0; n < 8; n++)
        #pragma unroll
        for (int e = 0; e < 4; e++) oacc[n][e] = 0.0f;
    float l0 = 0.0f, l1 = 0.0f;

    for (int kt = 0; kt < 32; kt++) {
        int buf = kt & 1;
        CPWAIT0();
        __syncthreads();
        if (kt < 31) issue(kt + 1, buf ^ 1);

        u32 KhB = smS + 36864 + buf * 9216;
        u32 VhB = smS + 55296 + buf * 9216;

        // ---- S = Q K^T  (64 kv cols), 2-term fp16: QhK + QlK ----
        float sacc[8][4];
        #pragma unroll
        for (int n = 0; n < 8; n++)
            #pragma unroll
            for (int e = 0; e < 4; e++) sacc[n][e] = 0.0f;

        #pragma unroll
        for (int kc2 = 0; kc2 < 2; kc2++) {
            u32 qal[2][4];
            ldmx4(qal[0], QlS + aOff + kc2 * 64);
            ldmx4(qal[1], QlS + aOff + kc2 * 64 + 32);
            #pragma unroll
            for (int ntg = 0; ntg < 2; ntg++) {
                u32 bf[4][4];
                #pragma unroll
                for (int j = 0; j < 4; j++)
                    ldmx4(bf[j], KhB + kOff + (ntg * 4 + j) * 8 * 144 + kc2 * 64);
                #pragma unroll
                for (int j = 0; j < 4; j++) mma16816h(sacc[ntg * 4 + j], qah[2 * kc2],     bf[j][0], bf[j][1]);
                #pragma unroll
                for (int j = 0; j < 4; j++) mma16816h(sacc[ntg * 4 + j], qah[2 * kc2 + 1], bf[j][2], bf[j][3]);
                #pragma unroll
                for (int j = 0; j < 4; j++) mma16816h(sacc[ntg * 4 + j], qal[0], bf[j][0], bf[j][1]);
                #pragma unroll
                for (int j = 0; j < 4; j++) mma16816h(sacc[ntg * 4 + j], qal[1], bf[j][2], bf[j][3]);
            }
        }

        // ---- softmax numerators: p = 2^s ----
        #pragma unroll
        for (int nt = 0; nt < 8; nt++) {
            sacc[nt][0] = ex2f(sacc[nt][0]);
            sacc[nt][1] = ex2f(sacc[nt][1]);
            sacc[nt][2] = ex2f(sacc[nt][2]);
            sacc[nt][3] = ex2f(sacc[nt][3]);
            l0 += sacc[nt][0] + sacc[nt][1];
            l1 += sacc[nt][2] + sacc[nt][3];
        }

        // ---- O += P V  (1-term fp16) ----
        #pragma unroll
        for (int c2 = 0; c2 < 2; c2++) {
            u32 pah[2][4];
            #pragma unroll
            for (int cc = 0; cc < 2; cc++) {
                int c = 2 * c2 + cc;
                pah[cc][0] = pack2h(sacc[2 * c][0],     sacc[2 * c][1]);
                pah[cc][1] = pack2h(sacc[2 * c][2],     sacc[2 * c][3]);
                pah[cc][2] = pack2h(sacc[2 * c + 1][0], sacc[2 * c + 1][1]);
                pah[cc][3] = pack2h(sacc[2 * c + 1][2], sacc[2 * c + 1][3]);
            }
            #pragma unroll
            for (int dtg = 0; dtg < 2; dtg++) {
                u32 vf[4][4];
                #pragma unroll
                for (int j = 0; j < 4; j++)
                    ldmx4(vf[j], VhB + kOff + (dtg * 4 + j) * 8 * 144 + c2 * 64);
                #pragma unroll
                for (int j = 0; j < 4; j++) mma16816h(oacc[dtg * 4 + j], pah[0], vf[j][0], vf[j][1]);
                #pragma unroll
                for (int j = 0; j < 4; j++) mma16816h(oacc[dtg * 4 + j], pah[1], vf[j][2], vf[j][3]);
            }
        }
        __syncthreads();
    }

    // row-sum reduce across the 4 threads of each row group
    l0 += __shfl_xor_sync(0xffffffffu, l0, 1);
    l0 += __shfl_xor_sync(0xffffffffu, l0, 2);
    l1 += __shfl_xor_sync(0xffffffffu, l1, 1);
    l1 += __shfl_xor_sync(0xffffffffu, l1, 2);
    float inv0 = 1.0f / l0, inv1 = 1.0f / l1;

    int b = bh >> 3, h = bh & 7;
    int s = q0 + w * 16 + g;
    float* o0 = out + ((b * 2048 + s) * 8 + h) * 64;
    float* o1 = out + ((b * 2048 + s + 8) * 8 + h) * 64;
    #pragma unroll
    for (int dt = 0; dt < 8; dt++) {
        *(float2*)(o0 + dt * 8 + 2 * tg) = make_float2(oacc[dt][0] * inv0, oacc[dt][1] * inv0);
        *(float2*)(o1 + dt * 8 + 2 * tg) = make_float2(oacc[dt][2] * inv1, oacc[dt][3] * inv1);
    }
}

extern "C" void kernel_launch(void* const* d_in, const int* in_sizes, int n_in,
                              void* d_out, int out_size)
{
    const float* x  = (const float*)d_in[0];
    const float* Wq = (const float*)d_in[1];
    const float* Wk = (const float*)d_in[2];
    const float* Wv = (const float*)d_in[3];
    float* out = (float*)d_out;

    cudaFuncSetAttribute(qkv_mma_kernel,  cudaFuncAttributeMaxDynamicSharedMemorySize, QK_SMEM);
    cudaFuncSetAttribute(attn_mma_kernel, cudaFuncAttributeMaxDynamicSharedMemorySize, AT_SMEM);

    split_x_kernel<<<512, 256>>>(x);
    split_w_kernel<<<24, 256>>>(Wq, Wk, Wv);
    qkv_mma_kernel<<<dim3(64, 24), 256, QK_SMEM>>>();
    attn_mma_kernel<<<dim3(16, 32), 256, AT_SMEM>>>(out);
}